// round 12
// baseline (speedup 1.0000x reference)
#include <cuda_runtime.h>
#include <cuda_fp16.h>
#include <math.h>
#include <stdint.h>

// Problem constants
#define BSZ    32
#define NSEQ   256
#define HDIM   512
#define NHEADS 8
#define DHEAD  64
#define FDIM   2048
#define LNUM   8
#define MROWS  (BSZ * NSEQ)   // 8192
#define NBH    (BSZ * NHEADS) // 256

// ---------------------------------------------------------------------------
// Scratch (static device globals; no runtime allocation allowed)
// Activations in fp16; residual stream stays fp32 in d_out.
// ---------------------------------------------------------------------------
__device__ __half g_y  [MROWS * HDIM];
__device__ __half g_q  [MROWS * HDIM];
__device__ __half g_k  [MROWS * HDIM];
__device__ __half g_ctx[MROWS * HDIM];
__device__ __half g_ffn[MROWS * FDIM];
__device__ __half g_vt [NBH * DHEAD * NSEQ];    // per-head transposed V
// Transposed weights: Wt[n][k] = half(W[k][n])
__device__ __half g_wqt[LNUM * HDIM * HDIM];
__device__ __half g_wkt[LNUM * HDIM * HDIM];
__device__ __half g_wvt[LNUM * HDIM * HDIM];
__device__ __half g_wot[LNUM * HDIM * HDIM];
__device__ __half g_w1t[LNUM * HDIM * FDIM];
__device__ __half g_w2t[LNUM * FDIM * HDIM];

// ---------------------------------------------------------------------------
// Helpers
// ---------------------------------------------------------------------------
__device__ __forceinline__ void cp_async16(void* dst, const void* src) {
    uint32_t d;
    asm("{ .reg .u64 t; cvta.to.shared.u64 t, %1; cvt.u32.u64 %0, t; }"
        : "=r"(d) : "l"(dst));
    asm volatile("cp.async.cg.shared.global [%0], [%1], 16;" :: "r"(d), "l"(src));
}

#define CP_COMMIT() asm volatile("cp.async.commit_group;" ::: "memory")
#define CP_WAIT(n)  asm volatile("cp.async.wait_group %0;" :: "n"(n) : "memory")

// fp16 MMA m16n8k16, fp32 accumulate
__device__ __forceinline__ void mma_f16(float* d, const uint32_t* a, const uint32_t* b) {
    asm volatile(
        "mma.sync.aligned.m16n8k16.row.col.f32.f16.f16.f32 "
        "{%0,%1,%2,%3}, {%4,%5,%6,%7}, {%8,%9}, {%0,%1,%2,%3};"
        : "+f"(d[0]), "+f"(d[1]), "+f"(d[2]), "+f"(d[3])
        : "r"(a[0]), "r"(a[1]), "r"(a[2]), "r"(a[3]), "r"(b[0]), "r"(b[1]));
}

// ---------------------------------------------------------------------------
// fp16 tile loader: 128 rows x 64 halves (128 B/row), swizzled 16B chunks:
// chunk ck of row r lands at r*128 + ((ck ^ (r&7)) * 16)
// ---------------------------------------------------------------------------
__device__ __forceinline__ void load_tile128h(const __half* __restrict__ base, int lda,
                                              int c, char* sdst, int tid) {
    const __half* p = base + c * 64;
    #pragma unroll
    for (int i = 0; i < 8; i++) {
        const int id  = tid + i * 128;
        const int row = id >> 3;
        const int ck  = id & 7;
        const int off = row * 128 + ((ck ^ (row & 7)) * 16);
        cp_async16(sdst + off, p + (size_t)row * lda + ck * 8);
    }
}

// ---------------------------------------------------------------------------
// GEMM core: 128x128 tile, BK=64 halves, 128 threads (4 warps 2x2, 64x64),
// 3-stage cp.async pipeline, single __syncthreads per chunk,
// ks-level double-buffered fragments (crossbar/tensor overlap).
// ---------------------------------------------------------------------------
#define TILE_B    16384                 // 128 x 64 halves
#define STAGE_B   32768
#define GSMEM3    (3 * STAGE_B)         // 98304

__device__ __forceinline__ void gemm_main_h(const __half* __restrict__ A, int lda,
                                            const __half* __restrict__ B, int ldb,
                                            int K, char* smem, int tid,
                                            float (&d)[4][8][4]) {
    const int warp   = tid >> 5;
    const int lane   = tid & 31;
    const int warp_m = (warp >> 1) * 64;
    const int warp_n = (warp & 1) * 64;
    const int row    = lane >> 2;
    const int col    = lane & 3;

    #pragma unroll
    for (int mt = 0; mt < 4; mt++)
        #pragma unroll
        for (int nt = 0; nt < 8; nt++)
            #pragma unroll
            for (int j = 0; j < 4; j++) d[mt][nt][j] = 0.0f;

    const int nch = K / 64;
    load_tile128h(A, lda, 0, smem, tid);
    load_tile128h(B, ldb, 0, smem + TILE_B, tid);
    CP_COMMIT();
    load_tile128h(A, lda, 1, smem + STAGE_B, tid);
    load_tile128h(B, ldb, 1, smem + STAGE_B + TILE_B, tid);
    CP_COMMIT();

    for (int c = 0; c < nch; c++) {
        if (c + 1 < nch) CP_WAIT(1);
        else             CP_WAIT(0);
        __syncthreads();

        if (c + 2 < nch) {
            char* st = smem + ((c + 2) % 3) * STAGE_B;
            load_tile128h(A, lda, c + 2, st, tid);
            load_tile128h(B, ldb, c + 2, st + TILE_B, tid);
            CP_COMMIT();
        }

        const char* Asb = smem + (c % 3) * STAGE_B;
        const char* Bsb = Asb + TILE_B;

        // ks-pipelined fragment buffers
        uint32_t a[2][4][4], b[2][8][2];

        #define LOAD_FRAGS(buf, ksv) do {                                      \
            const int _ck   = (ksv) * 2;                                       \
            const int _swz0 = ((_ck ^ (row & 7)) * 16) + 4 * col;              \
            const int _swz1 = (((_ck + 1) ^ (row & 7)) * 16) + 4 * col;        \
            _Pragma("unroll")                                                  \
            for (int mt = 0; mt < 4; mt++) {                                   \
                const char* ap0 = Asb + (warp_m + mt * 16 + row) * 128;        \
                const char* ap8 = ap0 + 8 * 128;                               \
                a[buf][mt][0] = *(const uint32_t*)(ap0 + _swz0);               \
                a[buf][mt][1] = *(const uint32_t*)(ap8 + _swz0);               \
                a[buf][mt][2] = *(const uint32_t*)(ap0 + _swz1);               \
                a[buf][mt][3] = *(const uint32_t*)(ap8 + _swz1);               \
            }                                                                  \
            _Pragma("unroll")                                                  \
            for (int nt = 0; nt < 8; nt++) {                                   \
                const char* bp = Bsb + (warp_n + nt * 8 + row) * 128;          \
                b[buf][nt][0] = *(const uint32_t*)(bp + _swz0);                \
                b[buf][nt][1] = *(const uint32_t*)(bp + _swz1);                \
            }                                                                  \
        } while (0)

        LOAD_FRAGS(0, 0);
        #pragma unroll
        for (int ks = 0; ks < 4; ks++) {
            const int cur = ks & 1;
            if (ks < 3) LOAD_FRAGS(cur ^ 1, ks + 1);
            #pragma unroll
            for (int mt = 0; mt < 4; mt++)
                #pragma unroll
                for (int nt = 0; nt < 8; nt++)
                    mma_f16(d[mt][nt], a[cur][mt], b[cur][nt]);
        }
        #undef LOAD_FRAGS
    }
}

// ---------------------------------------------------------------------------
// Generic GEMM kernels (fp16 in, weights pre-transposed)
//   EPI 2: half(gelu(acc + bias)) -> half C   EPI 3: fp32 C += acc + bias
// ---------------------------------------------------------------------------
template <int EPI>
__global__ __launch_bounds__(128, 2)
void tgemm_kernel(const __half* __restrict__ A, const __half* __restrict__ Bt,
                  const float* __restrict__ bias, void* __restrict__ Cv,
                  int Ncols, int K) {
    extern __shared__ __align__(16) char smem[];
    const int tid  = threadIdx.x;
    const int warp = tid >> 5;
    const int lane = tid & 31;
    const int m0 = blockIdx.y * 128;
    const int n0 = blockIdx.x * 128;

    float d[4][8][4];
    gemm_main_h(A + (size_t)m0 * K, K, Bt + (size_t)n0 * K, K, K, smem, tid, d);

    const int warp_m = (warp >> 1) * 64;
    const int warp_n = (warp & 1) * 64;
    const int row = lane >> 2, col = lane & 3;

    #pragma unroll
    for (int nt = 0; nt < 8; nt++) {
        const int nb = n0 + warp_n + nt * 8 + col * 2;
        const float2 bv = *(const float2*)(bias + nb);
        #pragma unroll
        for (int mt = 0; mt < 4; mt++) {
            const int m1 = m0 + warp_m + mt * 16 + row;
            #pragma unroll
            for (int half_i = 0; half_i < 2; half_i++) {
                const int mr = m1 + half_i * 8;
                float v0 = d[mt][nt][half_i * 2 + 0] + bv.x;
                float v1 = d[mt][nt][half_i * 2 + 1] + bv.y;
                if (EPI == 2) {
                    v0 = 0.5f * v0 * (1.0f + erff(v0 * 0.70710678118654752f));
                    v1 = 0.5f * v1 * (1.0f + erff(v1 * 0.70710678118654752f));
                    __half* crow = (__half*)Cv + (size_t)mr * Ncols + nb;
                    *(__half2*)crow = __floats2half2_rn(v0, v1);
                } else {
                    float* crow = (float*)Cv + (size_t)mr * Ncols + nb;
                    const float2 old = *(const float2*)crow;
                    *(float2*)crow = make_float2(v0 + old.x, v1 + old.y);
                }
            }
        }
    }
}

// ---------------------------------------------------------------------------
// Fused QKV projection: grid.x = 12 -> (sel = x>>2) in {q,k,v}, n0 = (x&3)*128
// Q: scaled fp16 out.  K: fp16 out.  V: written TRANSPOSED per-head into vt.
// ---------------------------------------------------------------------------
__global__ __launch_bounds__(128, 2)
void qkv_kernel(const __half* __restrict__ A,
                const __half* __restrict__ wqt, const __half* __restrict__ wkt,
                const __half* __restrict__ wvt,
                const float* __restrict__ bq, const float* __restrict__ bk,
                const float* __restrict__ bv,
                __half* __restrict__ q, __half* __restrict__ k,
                __half* __restrict__ vt) {
    extern __shared__ __align__(16) char smem[];
    const int tid  = threadIdx.x;
    const int warp = tid >> 5;
    const int lane = tid & 31;
    const int sel = blockIdx.x >> 2;
    const int n0  = (blockIdx.x & 3) * 128;
    const int m0  = blockIdx.y * 128;

    const __half* Bt  = (sel == 0) ? wqt : (sel == 1) ? wkt : wvt;
    const float* bias = (sel == 0) ? bq  : (sel == 1) ? bk  : bv;
    const float scale = (sel == 0) ? 0.125f : 1.0f;

    float d[4][8][4];
    gemm_main_h(A + (size_t)m0 * HDIM, HDIM, Bt + (size_t)n0 * HDIM, HDIM, HDIM,
                smem, tid, d);

    const int warp_m = (warp >> 1) * 64;
    const int warp_n = (warp & 1) * 64;
    const int row = lane >> 2, col = lane & 3;

    if (sel < 2) {
        __half* C = (sel == 0) ? q : k;
        #pragma unroll
        for (int nt = 0; nt < 8; nt++) {
            const int nb = n0 + warp_n + nt * 8 + col * 2;
            const float2 bvv = *(const float2*)(bias + nb);
            #pragma unroll
            for (int mt = 0; mt < 4; mt++) {
                const int m1 = m0 + warp_m + mt * 16 + row;
                #pragma unroll
                for (int half_i = 0; half_i < 2; half_i++) {
                    __half* crow = C + (size_t)(m1 + half_i * 8) * HDIM + nb;
                    const float v0 = (d[mt][nt][half_i * 2 + 0] + bvv.x) * scale;
                    const float v1 = (d[mt][nt][half_i * 2 + 1] + bvv.y) * scale;
                    *(__half2*)crow = __floats2half2_rn(v0, v1);
                }
            }
        }
    } else {
        // V: write transposed vt[bh][d][j], bh = b*8 + (nb>>6), d = nb&63, j = m&255
        #pragma unroll
        for (int nt = 0; nt < 8; nt++) {
            const int nb = n0 + warp_n + nt * 8 + col * 2;
            const float2 bvv = *(const float2*)(bias + nb);
            const int h  = nb >> 6;
            const int dd = nb & 63;
            #pragma unroll
            for (int mt = 0; mt < 4; mt++) {
                const int m1 = m0 + warp_m + mt * 16 + row;
                #pragma unroll
                for (int half_i = 0; half_i < 2; half_i++) {
                    const int m = m1 + half_i * 8;
                    const int bb = m >> 8;
                    const int jj = m & 255;
                    __half* base = vt + ((size_t)(bb * 8 + h) * DHEAD) * NSEQ + jj;
                    base[(size_t)dd * NSEQ] =
                        __float2half_rn(d[mt][nt][half_i * 2 + 0] + bvv.x);
                    base[(size_t)(dd + 1) * NSEQ] =
                        __float2half_rn(d[mt][nt][half_i * 2 + 1] + bvv.y);
                }
            }
        }
    }
}

// ---------------------------------------------------------------------------
// Fused flash attention (fp16 operands): ctx = softmax(Q·K^T + bias) · V
// Grid (2 q-tiles, 256 bh), 256 threads (8 warps x 16 q-rows).
// smem: [0,16K) Q (then per-warp P); [16K,32K) stage0 (K 8K | V 8K); [32K,48K) stage1
// ---------------------------------------------------------------------------
#define FA_STAGE 16384
#define FA_SMEM  (16384 + 2 * FA_STAGE)   // 49152

__device__ __forceinline__ void load_kv_h(const __half* __restrict__ Kb,
                                          const __half* __restrict__ Vb,
                                          int j0, char* st, int tid) {
    char* Ks = st;
    char* Vs = st + 8192;
    #pragma unroll
    for (int i = 0; i < 2; i++) {
        const int id = tid + i * 256;     // 0..511
        const int r  = id >> 3;           // 0..63
        const int ck = id & 7;
        const int off = r * 128 + ((ck ^ (r & 7)) * 16);
        cp_async16(Ks + off, Kb + (size_t)(j0 + r) * HDIM + ck * 8);
        cp_async16(Vs + off, Vb + (size_t)r * NSEQ + j0 + ck * 8);
    }
}

__global__ __launch_bounds__(256, 2)
void fattn_kernel(const __half* __restrict__ q, const __half* __restrict__ k,
                  const __half* __restrict__ vt, const float* __restrict__ attn_bias,
                  __half* __restrict__ ctx) {
    extern __shared__ __align__(16) char smem[];
    char* QP    = smem;            // 128 rows x 128 B  (Q, later per-warp P)
    char* stage = smem + 16384;

    const int tid  = threadIdx.x;
    const int warp = tid >> 5;
    const int lane = tid & 31;
    const int row  = lane >> 2;
    const int col  = lane & 3;
    const int bh = blockIdx.y;
    const int b  = bh >> 3, h = bh & 7;
    const int m0 = blockIdx.x * 128;

    const __half* Qb = q  + (size_t)b * NSEQ * HDIM + (size_t)m0 * HDIM + h * DHEAD;
    const __half* Kb = k  + (size_t)b * NSEQ * HDIM + h * DHEAD;
    const __half* Vb = vt + (size_t)bh * DHEAD * NSEQ;

    // Stage Q: 128 rows x 64 halves, swizzled
    #pragma unroll
    for (int i = 0; i < 4; i++) {
        const int id = tid + i * 256;     // 0..1023
        const int r  = id >> 3;           // 0..127
        const int ck = id & 7;
        const int off = r * 128 + ((ck ^ (r & 7)) * 16);
        cp_async16(QP + off, Qb + (size_t)r * HDIM + ck * 8);
    }
    CP_COMMIT();
    load_kv_h(Kb, Vb, 0, stage, tid);
    CP_COMMIT();

    // Wait for Q (KV0 still in flight), extract Q fragments
    CP_WAIT(1);
    __syncthreads();
    uint32_t aq[4][4];
    #pragma unroll
    for (int ks = 0; ks < 4; ks++) {
        const int ck   = ks * 2;
        const int swz0 = ((ck ^ (row & 7)) * 16) + 4 * col;
        const int swz1 = (((ck + 1) ^ (row & 7)) * 16) + 4 * col;
        const char* ap0 = QP + (warp * 16 + row) * 128;
        const char* ap8 = ap0 + 8 * 128;
        aq[ks][0] = *(const uint32_t*)(ap0 + swz0);
        aq[ks][1] = *(const uint32_t*)(ap8 + swz0);
        aq[ks][2] = *(const uint32_t*)(ap0 + swz1);
        aq[ks][3] = *(const uint32_t*)(ap8 + swz1);
    }
    __syncthreads();   // Q region now reusable as P buffer

    float m0r = -1e30f, m1r = -1e30f, l0 = 0.0f, l1 = 0.0f;
    float cacc[8][4];
    #pragma unroll
    for (int nt = 0; nt < 8; nt++)
        #pragma unroll
        for (int j = 0; j < 4; j++) cacc[nt][j] = 0.0f;

    const float* bias_b = attn_bias + (size_t)bh * NSEQ * NSEQ
                        + (size_t)(m0 + warp * 16 + row) * NSEQ;
    char* Pw = QP + warp * 2048;   // per-warp 16 rows x 128 B

    for (int c = 0; c < 4; c++) {
        CP_WAIT(0);
        __syncthreads();
        if (c < 3) {
            load_kv_h(Kb, Vb, (c + 1) * 64, stage + ((c + 1) & 1) * FA_STAGE, tid);
            CP_COMMIT();
        }

        const char* Ksb = stage + (c & 1) * FA_STAGE;
        const char* Vsb = Ksb + 8192;

        // S = Q · K^T over this 64-key chunk
        float s[8][4];
        #pragma unroll
        for (int nt = 0; nt < 8; nt++)
            #pragma unroll
            for (int j = 0; j < 4; j++) s[nt][j] = 0.0f;

        #pragma unroll
        for (int ks = 0; ks < 4; ks++) {
            const int ck   = ks * 2;
            const int swz0 = ((ck ^ (row & 7)) * 16) + 4 * col;
            const int swz1 = (((ck + 1) ^ (row & 7)) * 16) + 4 * col;
            uint32_t bfr[8][2];
            #pragma unroll
            for (int nt = 0; nt < 8; nt++) {
                const char* bp = Ksb + (nt * 8 + row) * 128;
                bfr[nt][0] = *(const uint32_t*)(bp + swz0);
                bfr[nt][1] = *(const uint32_t*)(bp + swz1);
            }
            #pragma unroll
            for (int nt = 0; nt < 8; nt++)
                mma_f16(s[nt], aq[ks], bfr[nt]);
        }

        // + bias, chunk row-max
        float mx0 = -1e30f, mx1 = -1e30f;
        #pragma unroll
        for (int nt = 0; nt < 8; nt++) {
            const float* bp = bias_b + c * 64 + nt * 8 + 2 * col;
            const float2 b0 = *(const float2*)bp;
            const float2 b1 = *(const float2*)(bp + 8 * NSEQ);
            s[nt][0] += b0.x; s[nt][1] += b0.y;
            s[nt][2] += b1.x; s[nt][3] += b1.y;
            mx0 = fmaxf(mx0, fmaxf(s[nt][0], s[nt][1]));
            mx1 = fmaxf(mx1, fmaxf(s[nt][2], s[nt][3]));
        }
        mx0 = fmaxf(mx0, __shfl_xor_sync(0xffffffffu, mx0, 1));
        mx0 = fmaxf(mx0, __shfl_xor_sync(0xffffffffu, mx0, 2));
        mx1 = fmaxf(mx1, __shfl_xor_sync(0xffffffffu, mx1, 1));
        mx1 = fmaxf(mx1, __shfl_xor_sync(0xffffffffu, mx1, 2));

        const float mn0 = fmaxf(m0r, mx0);
        const float mn1 = fmaxf(m1r, mx1);
        const float f0 = __expf(m0r - mn0);
        const float f1 = __expf(m1r - mn1);
        m0r = mn0; m1r = mn1;

        float sum0 = 0.0f, sum1 = 0.0f;
        #pragma unroll
        for (int nt = 0; nt < 8; nt++) {
            s[nt][0] = __expf(s[nt][0] - mn0);
            s[nt][1] = __expf(s[nt][1] - mn0);
            s[nt][2] = __expf(s[nt][2] - mn1);
            s[nt][3] = __expf(s[nt][3] - mn1);
            sum0 += s[nt][0] + s[nt][1];
            sum1 += s[nt][2] + s[nt][3];
        }
        l0 = l0 * f0 + sum0;
        l1 = l1 * f1 + sum1;
        #pragma unroll
        for (int nt = 0; nt < 8; nt++) {
            cacc[nt][0] *= f0; cacc[nt][1] *= f0;
            cacc[nt][2] *= f1; cacc[nt][3] *= f1;
        }

        // Store P tile (warp-private, 16 rows x 64 halves, swizzled)
        #pragma unroll
        for (int nt = 0; nt < 8; nt++) {
            const int swzp = ((nt ^ (row & 7)) * 16) + 4 * col;
            *(__half2*)(Pw + row * 128 + swzp) =
                __floats2half2_rn(s[nt][0], s[nt][1]);
            *(__half2*)(Pw + (row + 8) * 128 + swzp) =
                __floats2half2_rn(s[nt][2], s[nt][3]);
        }
        __syncwarp();

        // ctx += P · V
        #pragma unroll
        for (int ks = 0; ks < 4; ks++) {
            const int ck   = ks * 2;
            const int swz0 = ((ck ^ (row & 7)) * 16) + 4 * col;
            const int swz1 = (((ck + 1) ^ (row & 7)) * 16) + 4 * col;
            const char* pp0 = Pw + row * 128;
            const char* pp8 = pp0 + 8 * 128;
            uint32_t a[4];
            a[0] = *(const uint32_t*)(pp0 + swz0);
            a[1] = *(const uint32_t*)(pp8 + swz0);
            a[2] = *(const uint32_t*)(pp0 + swz1);
            a[3] = *(const uint32_t*)(pp8 + swz1);
            uint32_t bfr[8][2];
            #pragma unroll
            for (int nt = 0; nt < 8; nt++) {
                const char* bp = Vsb + (nt * 8 + row) * 128;
                bfr[nt][0] = *(const uint32_t*)(bp + swz0);
                bfr[nt][1] = *(const uint32_t*)(bp + swz1);
            }
            #pragma unroll
            for (int nt = 0; nt < 8; nt++)
                mma_f16(cacc[nt], a, bfr[nt]);
        }
        __syncwarp();
    }

    // Final normalize + write ctx [b][q][h*64+d] (fp16)
    l0 += __shfl_xor_sync(0xffffffffu, l0, 1);
    l0 += __shfl_xor_sync(0xffffffffu, l0, 2);
    l1 += __shfl_xor_sync(0xffffffffu, l1, 1);
    l1 += __shfl_xor_sync(0xffffffffu, l1, 2);
    const float inv0 = 1.0f / l0;
    const float inv1 = 1.0f / l1;

    __half* Cb = ctx + (size_t)b * NSEQ * HDIM + h * DHEAD
               + (size_t)(m0 + warp * 16 + row) * HDIM;
    #pragma unroll
    for (int nt = 0; nt < 8; nt++) {
        const int nb = nt * 8 + 2 * col;
        *(__half2*)(Cb + nb) =
            __floats2half2_rn(cacc[nt][0] * inv0, cacc[nt][1] * inv0);
        *(__half2*)(Cb + 8 * HDIM + nb) =
            __floats2half2_rn(cacc[nt][2] * inv1, cacc[nt][3] * inv1);
    }
}

// ---------------------------------------------------------------------------
// Weight transpose + fp16 convert: dst[n][k] = half(src[k][n]) per layer
// ---------------------------------------------------------------------------
__global__ void transpose_kernel(const float* __restrict__ src,
                                 __half* __restrict__ dst, int R, int C) {
    __shared__ float t[32][33];
    const size_t lo = (size_t)blockIdx.z * R * C;
    const int c0 = blockIdx.x * 32, r0 = blockIdx.y * 32;
    #pragma unroll
    for (int i = 0; i < 32; i += 8)
        t[threadIdx.y + i][threadIdx.x] =
            src[lo + (size_t)(r0 + threadIdx.y + i) * C + c0 + threadIdx.x];
    __syncthreads();
    #pragma unroll
    for (int i = 0; i < 32; i += 8)
        dst[lo + (size_t)(c0 + threadIdx.y + i) * R + r0 + threadIdx.x] =
            __float2half_rn(t[threadIdx.x][threadIdx.y + i]);
}

// ---------------------------------------------------------------------------
// LayerNorm: warp-per-row (8 rows per 256-thread block), float4 loads,
// pure shfl reductions, no __syncthreads. fp16 out via uint2 stores.
// ---------------------------------------------------------------------------
__global__ __launch_bounds__(256)
void ln_kernel(const float* __restrict__ x,
               const float* __restrict__ gs,
               const float* __restrict__ gb,
               __half* __restrict__ y) {
    const int warp = threadIdx.x >> 5;
    const int lane = threadIdx.x & 31;
    const int row  = blockIdx.x * 8 + warp;

    const float4* xr = (const float4*)(x + (size_t)row * HDIM);
    float4 v[4];
    float s = 0.0f;
    #pragma unroll
    for (int j = 0; j < 4; j++) {
        v[j] = xr[j * 32 + lane];
        s += v[j].x + v[j].y + v[j].z + v[j].w;
    }
    #pragma unroll
    for (int o = 16; o; o >>= 1) s += __shfl_xor_sync(0xffffffffu, s, o);
    const float mu = s * (1.0f / HDIM);

    float sq = 0.0f;
    #pragma unroll
    for (int j = 0; j < 4; j++) {
        v[j].x -= mu; v[j].y -= mu; v[j].z -= mu; v[j].w -= mu;
        sq += v[j].x * v[j].x + v[j].y * v[j].y + v[j].z * v[j].z + v[j].w * v[j].w;
    }
    #pragma unroll
    for (int o = 16; o; o >>= 1) sq += __shfl_xor_sync(0xffffffffu, sq, o);
    const float inv = rsqrtf(sq * (1.0f / HDIM) + 1e-5f);

    const float4* gs4 = (const float4*)gs;
    const float4* gb4 = (const float4*)gb;
    uint2* yr = (uint2*)(y + (size_t)row * HDIM);
    #pragma unroll
    for (int j = 0; j < 4; j++) {
        const int idx = j * 32 + lane;
        const float4 g = gs4[idx];
        const float4 bb = gb4[idx];
        const __half2 lo = __floats2half2_rn(v[j].x * inv * g.x + bb.x,
                                             v[j].y * inv * g.y + bb.y);
        const __half2 hi = __floats2half2_rn(v[j].z * inv * g.z + bb.z,
                                             v[j].w * inv * g.w + bb.w);
        uint2 pk;
        pk.x = *(const uint32_t*)&lo;
        pk.y = *(const uint32_t*)&hi;
        yr[idx] = pk;
    }
}

// ---------------------------------------------------------------------------
// Host launcher
// ---------------------------------------------------------------------------
extern "C" void kernel_launch(void* const* d_in, const int* in_sizes, int n_in,
                              void* d_out, int out_size) {
    const float* x_in      = (const float*)d_in[0];
    const float* attn_bias = (const float*)d_in[1];
    const float* ln1_s     = (const float*)d_in[2];
    const float* ln1_b     = (const float*)d_in[3];
    const float* wq        = (const float*)d_in[4];
    const float* bq        = (const float*)d_in[5];
    const float* wk        = (const float*)d_in[6];
    const float* bk        = (const float*)d_in[7];
    const float* wv        = (const float*)d_in[8];
    const float* bv        = (const float*)d_in[9];
    const float* wo        = (const float*)d_in[10];
    const float* bo        = (const float*)d_in[11];
    const float* ln2_s     = (const float*)d_in[12];
    const float* ln2_b     = (const float*)d_in[13];
    const float* w1        = (const float*)d_in[14];
    const float* b1        = (const float*)d_in[15];
    const float* w2        = (const float*)d_in[16];
    const float* b2        = (const float*)d_in[17];

    float* X = (float*)d_out;

    __half *yb, *qb, *kb, *cb, *fb, *vt;
    __half *wqt, *wkt, *wvt, *wot, *w1t, *w2t;
    cudaGetSymbolAddress((void**)&yb, g_y);
    cudaGetSymbolAddress((void**)&qb, g_q);
    cudaGetSymbolAddress((void**)&kb, g_k);
    cudaGetSymbolAddress((void**)&cb, g_ctx);
    cudaGetSymbolAddress((void**)&fb, g_ffn);
    cudaGetSymbolAddress((void**)&vt, g_vt);
    cudaGetSymbolAddress((void**)&wqt, g_wqt);
    cudaGetSymbolAddress((void**)&wkt, g_wkt);
    cudaGetSymbolAddress((void**)&wvt, g_wvt);
    cudaGetSymbolAddress((void**)&wot, g_wot);
    cudaGetSymbolAddress((void**)&w1t, g_w1t);
    cudaGetSymbolAddress((void**)&w2t, g_w2t);

    cudaFuncSetAttribute(tgemm_kernel<2>,
                         cudaFuncAttributeMaxDynamicSharedMemorySize, GSMEM3);
    cudaFuncSetAttribute(tgemm_kernel<3>,
                         cudaFuncAttributeMaxDynamicSharedMemorySize, GSMEM3);
    cudaFuncSetAttribute(qkv_kernel,
                         cudaFuncAttributeMaxDynamicSharedMemorySize, GSMEM3);
    cudaFuncSetAttribute(fattn_kernel,
                         cudaFuncAttributeMaxDynamicSharedMemorySize, FA_SMEM);

    cudaMemcpyAsync(X, x_in, (size_t)MROWS * HDIM * sizeof(float),
                    cudaMemcpyDeviceToDevice);

    // One-time weight transposes (+ fp16 convert)
    {
        const dim3 tb(32, 8);
        const dim3 gHH(HDIM / 32, HDIM / 32, LNUM);
        const dim3 gHF(FDIM / 32, HDIM / 32, LNUM);
        const dim3 gFH(HDIM / 32, FDIM / 32, LNUM);
        transpose_kernel<<<gHH, tb>>>(wq, wqt, HDIM, HDIM);
        transpose_kernel<<<gHH, tb>>>(wk, wkt, HDIM, HDIM);
        transpose_kernel<<<gHH, tb>>>(wv, wvt, HDIM, HDIM);
        transpose_kernel<<<gHH, tb>>>(wo, wot, HDIM, HDIM);
        transpose_kernel<<<gHF, tb>>>(w1, w1t, HDIM, FDIM);
        transpose_kernel<<<gFH, tb>>>(w2, w2t, FDIM, HDIM);
    }

    const dim3 gB(256);
    const dim3 tG(128);
    const dim3 gLN(MROWS / 8);                   // 1024 blocks, warp-per-row
    const dim3 gQKV(12, MROWS / 128);            // (12, 64)
    const dim3 gProj(HDIM / 128, MROWS / 128);   // (4, 64)
    const dim3 gFfn1(FDIM / 128, MROWS / 128);   // (16, 64)
    const dim3 gFA(NSEQ / 128, NBH);             // (2, 256)

    for (int l = 0; l < LNUM; l++) {
        const __half* wqt_l = wqt + (size_t)l * HDIM * HDIM;
        const __half* wkt_l = wkt + (size_t)l * HDIM * HDIM;
        const __half* wvt_l = wvt + (size_t)l * HDIM * HDIM;
        const __half* wot_l = wot + (size_t)l * HDIM * HDIM;
        const __half* w1t_l = w1t + (size_t)l * HDIM * FDIM;
        const __half* w2t_l = w2t + (size_t)l * FDIM * HDIM;

        // --- attention block ---
        ln_kernel<<<gLN, gB>>>(X, ln1_s + l * HDIM, ln1_b + l * HDIM, yb);
        qkv_kernel<<<gQKV, tG, GSMEM3>>>(yb, wqt_l, wkt_l, wvt_l,
                                         bq + l * HDIM, bk + l * HDIM, bv + l * HDIM,
                                         qb, kb, vt);
        fattn_kernel<<<gFA, gB, FA_SMEM>>>(qb, kb, vt, attn_bias, cb);
        tgemm_kernel<3><<<gProj, tG, GSMEM3>>>(cb, wot_l, bo + l * HDIM, X,
                                               HDIM, HDIM);

        // --- FFN block ---
        ln_kernel<<<gLN, gB>>>(X, ln2_s + l * HDIM, ln2_b + l * HDIM, yb);
        tgemm_kernel<2><<<gFfn1, tG, GSMEM3>>>(yb, w1t_l, b1 + l * FDIM, fb,
                                               FDIM, HDIM);
        tgemm_kernel<3><<<gProj, tG, GSMEM3>>>(fb, w2t_l, b2 + l * HDIM, X,
                                               HDIM, FDIM);
    }
}

// round 13
// speedup vs baseline: 1.0905x; 1.0905x over previous
#include <cuda_runtime.h>
#include <cuda_fp16.h>
#include <math.h>
#include <stdint.h>

// Problem constants
#define BSZ    32
#define NSEQ   256
#define HDIM   512
#define NHEADS 8
#define DHEAD  64
#define FDIM   2048
#define LNUM   8
#define MROWS  (BSZ * NSEQ)   // 8192
#define NBH    (BSZ * NHEADS) // 256

// ---------------------------------------------------------------------------
// Scratch (static device globals; no runtime allocation allowed)
// Activations in fp16; residual stream stays fp32 in d_out.
// ---------------------------------------------------------------------------
__device__ __half g_y  [MROWS * HDIM];
__device__ __half g_q  [MROWS * HDIM];
__device__ __half g_k  [MROWS * HDIM];
__device__ __half g_ctx[MROWS * HDIM];
__device__ __half g_ffn[MROWS * FDIM];
__device__ __half g_vt [NBH * DHEAD * NSEQ];    // per-head transposed V
// Transposed weights: Wt[n][k] = half(W[k][n])
__device__ __half g_wqt[LNUM * HDIM * HDIM];
__device__ __half g_wkt[LNUM * HDIM * HDIM];
__device__ __half g_wvt[LNUM * HDIM * HDIM];
__device__ __half g_wot[LNUM * HDIM * HDIM];
__device__ __half g_w1t[LNUM * HDIM * FDIM];
__device__ __half g_w2t[LNUM * FDIM * HDIM];

// ---------------------------------------------------------------------------
// Helpers
// ---------------------------------------------------------------------------
__device__ __forceinline__ void cp_async16(void* dst, const void* src) {
    uint32_t d;
    asm("{ .reg .u64 t; cvta.to.shared.u64 t, %1; cvt.u32.u64 %0, t; }"
        : "=r"(d) : "l"(dst));
    asm volatile("cp.async.cg.shared.global [%0], [%1], 16;" :: "r"(d), "l"(src));
}

#define CP_COMMIT() asm volatile("cp.async.commit_group;" ::: "memory")
#define CP_WAIT(n)  asm volatile("cp.async.wait_group %0;" :: "n"(n) : "memory")

// fp16 MMA m16n8k16, fp32 accumulate
__device__ __forceinline__ void mma_f16(float* d, const uint32_t* a, const uint32_t* b) {
    asm volatile(
        "mma.sync.aligned.m16n8k16.row.col.f32.f16.f16.f32 "
        "{%0,%1,%2,%3}, {%4,%5,%6,%7}, {%8,%9}, {%0,%1,%2,%3};"
        : "+f"(d[0]), "+f"(d[1]), "+f"(d[2]), "+f"(d[3])
        : "r"(a[0]), "r"(a[1]), "r"(a[2]), "r"(a[3]), "r"(b[0]), "r"(b[1]));
}

// ---------------------------------------------------------------------------
// fp16 tile loader: 128 rows x 64 halves (128 B/row), swizzled 16B chunks:
// chunk ck of row r lands at r*128 + ((ck ^ (r&7)) * 16)
// ---------------------------------------------------------------------------
__device__ __forceinline__ void load_tile128h(const __half* __restrict__ base, int lda,
                                              int c, char* sdst, int tid) {
    const __half* p = base + c * 64;
    #pragma unroll
    for (int i = 0; i < 8; i++) {
        const int id  = tid + i * 128;
        const int row = id >> 3;
        const int ck  = id & 7;
        const int off = row * 128 + ((ck ^ (row & 7)) * 16);
        cp_async16(sdst + off, p + (size_t)row * lda + ck * 8);
    }
}

// ---------------------------------------------------------------------------
// GEMM core: 128x128 tile, BK=64 halves, 128 threads (4 warps 2x2, 64x64),
// 3-stage cp.async pipeline, single __syncthreads per chunk.
// (Round-9/11 flat schedule — proven local optimum; do not re-pipeline.)
// ---------------------------------------------------------------------------
#define TILE_B    16384                 // 128 x 64 halves
#define STAGE_B   32768
#define GSMEM3    (3 * STAGE_B)         // 98304

__device__ __forceinline__ void gemm_main_h(const __half* __restrict__ A, int lda,
                                            const __half* __restrict__ B, int ldb,
                                            int K, char* smem, int tid,
                                            float (&d)[4][8][4]) {
    const int warp   = tid >> 5;
    const int lane   = tid & 31;
    const int warp_m = (warp >> 1) * 64;
    const int warp_n = (warp & 1) * 64;
    const int row    = lane >> 2;
    const int col    = lane & 3;

    #pragma unroll
    for (int mt = 0; mt < 4; mt++)
        #pragma unroll
        for (int nt = 0; nt < 8; nt++)
            #pragma unroll
            for (int j = 0; j < 4; j++) d[mt][nt][j] = 0.0f;

    const int nch = K / 64;
    load_tile128h(A, lda, 0, smem, tid);
    load_tile128h(B, ldb, 0, smem + TILE_B, tid);
    CP_COMMIT();
    load_tile128h(A, lda, 1, smem + STAGE_B, tid);
    load_tile128h(B, ldb, 1, smem + STAGE_B + TILE_B, tid);
    CP_COMMIT();

    for (int c = 0; c < nch; c++) {
        if (c + 1 < nch) CP_WAIT(1);
        else             CP_WAIT(0);
        __syncthreads();

        if (c + 2 < nch) {
            char* st = smem + ((c + 2) % 3) * STAGE_B;
            load_tile128h(A, lda, c + 2, st, tid);
            load_tile128h(B, ldb, c + 2, st + TILE_B, tid);
            CP_COMMIT();
        }

        const char* Asb = smem + (c % 3) * STAGE_B;
        const char* Bsb = Asb + TILE_B;

        #pragma unroll
        for (int ks = 0; ks < 4; ks++) {
            const int ck   = ks * 2;
            const int swz0 = ((ck ^ (row & 7)) * 16) + 4 * col;
            const int swz1 = (((ck + 1) ^ (row & 7)) * 16) + 4 * col;

            uint32_t a[4][4];
            #pragma unroll
            for (int mt = 0; mt < 4; mt++) {
                const char* ap0 = Asb + (warp_m + mt * 16 + row) * 128;
                const char* ap8 = ap0 + 8 * 128;
                a[mt][0] = *(const uint32_t*)(ap0 + swz0);
                a[mt][1] = *(const uint32_t*)(ap8 + swz0);
                a[mt][2] = *(const uint32_t*)(ap0 + swz1);
                a[mt][3] = *(const uint32_t*)(ap8 + swz1);
            }
            uint32_t b[8][2];
            #pragma unroll
            for (int nt = 0; nt < 8; nt++) {
                const char* bp = Bsb + (warp_n + nt * 8 + row) * 128;
                b[nt][0] = *(const uint32_t*)(bp + swz0);
                b[nt][1] = *(const uint32_t*)(bp + swz1);
            }
            #pragma unroll
            for (int mt = 0; mt < 4; mt++)
                #pragma unroll
                for (int nt = 0; nt < 8; nt++)
                    mma_f16(d[mt][nt], a[mt], b[nt]);
        }
    }
}

// ---------------------------------------------------------------------------
// Generic GEMM kernels (fp16 in, weights pre-transposed)
//   EPI 2: half(gelu(acc + bias)) -> half C   EPI 3: fp32 C += acc + bias
// ---------------------------------------------------------------------------
template <int EPI>
__global__ __launch_bounds__(128, 2)
void tgemm_kernel(const __half* __restrict__ A, const __half* __restrict__ Bt,
                  const float* __restrict__ bias, void* __restrict__ Cv,
                  int Ncols, int K) {
    extern __shared__ __align__(16) char smem[];
    const int tid  = threadIdx.x;
    const int warp = tid >> 5;
    const int lane = tid & 31;
    const int m0 = blockIdx.y * 128;
    const int n0 = blockIdx.x * 128;

    float d[4][8][4];
    gemm_main_h(A + (size_t)m0 * K, K, Bt + (size_t)n0 * K, K, K, smem, tid, d);

    const int warp_m = (warp >> 1) * 64;
    const int warp_n = (warp & 1) * 64;
    const int row = lane >> 2, col = lane & 3;

    #pragma unroll
    for (int nt = 0; nt < 8; nt++) {
        const int nb = n0 + warp_n + nt * 8 + col * 2;
        const float2 bv = *(const float2*)(bias + nb);
        #pragma unroll
        for (int mt = 0; mt < 4; mt++) {
            const int m1 = m0 + warp_m + mt * 16 + row;
            #pragma unroll
            for (int half_i = 0; half_i < 2; half_i++) {
                const int mr = m1 + half_i * 8;
                float v0 = d[mt][nt][half_i * 2 + 0] + bv.x;
                float v1 = d[mt][nt][half_i * 2 + 1] + bv.y;
                if (EPI == 2) {
                    v0 = 0.5f * v0 * (1.0f + erff(v0 * 0.70710678118654752f));
                    v1 = 0.5f * v1 * (1.0f + erff(v1 * 0.70710678118654752f));
                    __half* crow = (__half*)Cv + (size_t)mr * Ncols + nb;
                    *(__half2*)crow = __floats2half2_rn(v0, v1);
                } else {
                    float* crow = (float*)Cv + (size_t)mr * Ncols + nb;
                    const float2 old = *(const float2*)crow;
                    *(float2*)crow = make_float2(v0 + old.x, v1 + old.y);
                }
            }
        }
    }
}

// ---------------------------------------------------------------------------
// Fused QKV projection: grid.x = 12 -> (sel = x>>2) in {q,k,v}, n0 = (x&3)*128
// Q: scaled fp16 out.  K: fp16 out.
// V: staged through smem (pipeline smem is dead post-mainloop) and written
//    TRANSPOSED per-head into vt with coalesced stores.
// ---------------------------------------------------------------------------
#define VT_STRIDE 144   // halves per staged row (288 B, 16B-aligned)

__global__ __launch_bounds__(128, 2)
void qkv_kernel(const __half* __restrict__ A,
                const __half* __restrict__ wqt, const __half* __restrict__ wkt,
                const __half* __restrict__ wvt,
                const float* __restrict__ bq, const float* __restrict__ bk,
                const float* __restrict__ bv,
                __half* __restrict__ q, __half* __restrict__ k,
                __half* __restrict__ vt) {
    extern __shared__ __align__(16) char smem[];
    const int tid  = threadIdx.x;
    const int warp = tid >> 5;
    const int lane = tid & 31;
    const int sel = blockIdx.x >> 2;
    const int n0  = (blockIdx.x & 3) * 128;
    const int m0  = blockIdx.y * 128;

    const __half* Bt  = (sel == 0) ? wqt : (sel == 1) ? wkt : wvt;
    const float* bias = (sel == 0) ? bq  : (sel == 1) ? bk  : bv;
    const float scale = (sel == 0) ? 0.125f : 1.0f;

    float d[4][8][4];
    gemm_main_h(A + (size_t)m0 * HDIM, HDIM, Bt + (size_t)n0 * HDIM, HDIM, HDIM,
                smem, tid, d);

    const int warp_m = (warp >> 1) * 64;
    const int warp_n = (warp & 1) * 64;
    const int row = lane >> 2, col = lane & 3;

    if (sel < 2) {
        __half* C = (sel == 0) ? q : k;
        #pragma unroll
        for (int nt = 0; nt < 8; nt++) {
            const int nb = n0 + warp_n + nt * 8 + col * 2;
            const float2 bvv = *(const float2*)(bias + nb);
            #pragma unroll
            for (int mt = 0; mt < 4; mt++) {
                const int m1 = m0 + warp_m + mt * 16 + row;
                #pragma unroll
                for (int half_i = 0; half_i < 2; half_i++) {
                    __half* crow = C + (size_t)(m1 + half_i * 8) * HDIM + nb;
                    const float v0 = (d[mt][nt][half_i * 2 + 0] + bvv.x) * scale;
                    const float v1 = (d[mt][nt][half_i * 2 + 1] + bvv.y) * scale;
                    *(__half2*)crow = __floats2half2_rn(v0, v1);
                }
            }
        }
    } else {
        // V path: stage [n_local][m_local] tile in smem, then coalesced
        // transposed write-out to vt[bh][d][j].
        __syncthreads();   // mainloop fragment reads fully drained
        __half* tp = (__half*)smem;   // [128][VT_STRIDE]
        #pragma unroll
        for (int nt = 0; nt < 8; nt++) {
            const int nl = warp_n + nt * 8 + col * 2;   // 0..127 local n
            const float2 bvv = *(const float2*)(bias + n0 + nl);
            #pragma unroll
            for (int mt = 0; mt < 4; mt++) {
                #pragma unroll
                for (int half_i = 0; half_i < 2; half_i++) {
                    const int ml = warp_m + mt * 16 + row + half_i * 8;
                    tp[nl * VT_STRIDE + ml] =
                        __float2half_rn(d[mt][nt][half_i * 2 + 0] + bvv.x);
                    tp[(nl + 1) * VT_STRIDE + ml] =
                        __float2half_rn(d[mt][nt][half_i * 2 + 1] + bvv.y);
                }
            }
        }
        __syncthreads();

        // Write-out: 128 rows (n_local), each 128 halves (256 B) contiguous
        // in vt. 16 threads per row x 16B chunks; 8 rows per pass.
        const int bb = m0 >> 8;        // batch
        const int j0 = m0 & 255;       // seq offset within batch
        const int chunk = tid & 15;    // 16B chunk within row
        const int rsub  = tid >> 4;    // 0..7
        #pragma unroll
        for (int it = 0; it < 16; it++) {
            const int nl = it * 8 + rsub;        // 0..127 local n
            const int h  = (n0 + nl) >> 6;
            const int dd = (n0 + nl) & 63;
            const uint4 val = *(const uint4*)(tp + nl * VT_STRIDE + chunk * 8);
            __half* dst = vt + ((size_t)(bb * 8 + h) * DHEAD + dd) * NSEQ + j0;
            *(uint4*)(dst + chunk * 8) = val;
        }
    }
}

// ---------------------------------------------------------------------------
// Fused flash attention (fp16 operands): ctx = softmax(Q·K^T + bias) · V
// Grid (2 q-tiles, 256 bh), 256 threads (8 warps x 16 q-rows).
// smem: [0,16K) Q (then per-warp P); [16K,32K) stage0 (K 8K | V 8K); [32K,48K) stage1
// ---------------------------------------------------------------------------
#define FA_STAGE 16384
#define FA_SMEM  (16384 + 2 * FA_STAGE)   // 49152

__device__ __forceinline__ void load_kv_h(const __half* __restrict__ Kb,
                                          const __half* __restrict__ Vb,
                                          int j0, char* st, int tid) {
    char* Ks = st;
    char* Vs = st + 8192;
    #pragma unroll
    for (int i = 0; i < 2; i++) {
        const int id = tid + i * 256;     // 0..511
        const int r  = id >> 3;           // 0..63
        const int ck = id & 7;
        const int off = r * 128 + ((ck ^ (r & 7)) * 16);
        cp_async16(Ks + off, Kb + (size_t)(j0 + r) * HDIM + ck * 8);
        cp_async16(Vs + off, Vb + (size_t)r * NSEQ + j0 + ck * 8);
    }
}

__global__ __launch_bounds__(256, 2)
void fattn_kernel(const __half* __restrict__ q, const __half* __restrict__ k,
                  const __half* __restrict__ vt, const float* __restrict__ attn_bias,
                  __half* __restrict__ ctx) {
    extern __shared__ __align__(16) char smem[];
    char* QP    = smem;            // 128 rows x 128 B  (Q, later per-warp P)
    char* stage = smem + 16384;

    const int tid  = threadIdx.x;
    const int warp = tid >> 5;
    const int lane = tid & 31;
    const int row  = lane >> 2;
    const int col  = lane & 3;
    const int bh = blockIdx.y;
    const int b  = bh >> 3, h = bh & 7;
    const int m0 = blockIdx.x * 128;

    const __half* Qb = q  + (size_t)b * NSEQ * HDIM + (size_t)m0 * HDIM + h * DHEAD;
    const __half* Kb = k  + (size_t)b * NSEQ * HDIM + h * DHEAD;
    const __half* Vb = vt + (size_t)bh * DHEAD * NSEQ;

    // Stage Q: 128 rows x 64 halves, swizzled
    #pragma unroll
    for (int i = 0; i < 4; i++) {
        const int id = tid + i * 256;     // 0..1023
        const int r  = id >> 3;           // 0..127
        const int ck = id & 7;
        const int off = r * 128 + ((ck ^ (r & 7)) * 16);
        cp_async16(QP + off, Qb + (size_t)r * HDIM + ck * 8);
    }
    CP_COMMIT();
    load_kv_h(Kb, Vb, 0, stage, tid);
    CP_COMMIT();

    // Wait for Q (KV0 still in flight), extract Q fragments
    CP_WAIT(1);
    __syncthreads();
    uint32_t aq[4][4];
    #pragma unroll
    for (int ks = 0; ks < 4; ks++) {
        const int ck   = ks * 2;
        const int swz0 = ((ck ^ (row & 7)) * 16) + 4 * col;
        const int swz1 = (((ck + 1) ^ (row & 7)) * 16) + 4 * col;
        const char* ap0 = QP + (warp * 16 + row) * 128;
        const char* ap8 = ap0 + 8 * 128;
        aq[ks][0] = *(const uint32_t*)(ap0 + swz0);
        aq[ks][1] = *(const uint32_t*)(ap8 + swz0);
        aq[ks][2] = *(const uint32_t*)(ap0 + swz1);
        aq[ks][3] = *(const uint32_t*)(ap8 + swz1);
    }
    __syncthreads();   // Q region now reusable as P buffer

    float m0r = -1e30f, m1r = -1e30f, l0 = 0.0f, l1 = 0.0f;
    float cacc[8][4];
    #pragma unroll
    for (int nt = 0; nt < 8; nt++)
        #pragma unroll
        for (int j = 0; j < 4; j++) cacc[nt][j] = 0.0f;

    const float* bias_b = attn_bias + (size_t)bh * NSEQ * NSEQ
                        + (size_t)(m0 + warp * 16 + row) * NSEQ;
    char* Pw = QP + warp * 2048;   // per-warp 16 rows x 128 B

    for (int c = 0; c < 4; c++) {
        CP_WAIT(0);
        __syncthreads();
        if (c < 3) {
            load_kv_h(Kb, Vb, (c + 1) * 64, stage + ((c + 1) & 1) * FA_STAGE, tid);
            CP_COMMIT();
        }

        const char* Ksb = stage + (c & 1) * FA_STAGE;
        const char* Vsb = Ksb + 8192;

        // S = Q · K^T over this 64-key chunk
        float s[8][4];
        #pragma unroll
        for (int nt = 0; nt < 8; nt++)
            #pragma unroll
            for (int j = 0; j < 4; j++) s[nt][j] = 0.0f;

        #pragma unroll
        for (int ks = 0; ks < 4; ks++) {
            const int ck   = ks * 2;
            const int swz0 = ((ck ^ (row & 7)) * 16) + 4 * col;
            const int swz1 = (((ck + 1) ^ (row & 7)) * 16) + 4 * col;
            uint32_t bfr[8][2];
            #pragma unroll
            for (int nt = 0; nt < 8; nt++) {
                const char* bp = Ksb + (nt * 8 + row) * 128;
                bfr[nt][0] = *(const uint32_t*)(bp + swz0);
                bfr[nt][1] = *(const uint32_t*)(bp + swz1);
            }
            #pragma unroll
            for (int nt = 0; nt < 8; nt++)
                mma_f16(s[nt], aq[ks], bfr[nt]);
        }

        // + bias, chunk row-max
        float mx0 = -1e30f, mx1 = -1e30f;
        #pragma unroll
        for (int nt = 0; nt < 8; nt++) {
            const float* bp = bias_b + c * 64 + nt * 8 + 2 * col;
            const float2 b0 = *(const float2*)bp;
            const float2 b1 = *(const float2*)(bp + 8 * NSEQ);
            s[nt][0] += b0.x; s[nt][1] += b0.y;
            s[nt][2] += b1.x; s[nt][3] += b1.y;
            mx0 = fmaxf(mx0, fmaxf(s[nt][0], s[nt][1]));
            mx1 = fmaxf(mx1, fmaxf(s[nt][2], s[nt][3]));
        }
        mx0 = fmaxf(mx0, __shfl_xor_sync(0xffffffffu, mx0, 1));
        mx0 = fmaxf(mx0, __shfl_xor_sync(0xffffffffu, mx0, 2));
        mx1 = fmaxf(mx1, __shfl_xor_sync(0xffffffffu, mx1, 1));
        mx1 = fmaxf(mx1, __shfl_xor_sync(0xffffffffu, mx1, 2));

        const float mn0 = fmaxf(m0r, mx0);
        const float mn1 = fmaxf(m1r, mx1);
        const float f0 = __expf(m0r - mn0);
        const float f1 = __expf(m1r - mn1);
        m0r = mn0; m1r = mn1;

        float sum0 = 0.0f, sum1 = 0.0f;
        #pragma unroll
        for (int nt = 0; nt < 8; nt++) {
            s[nt][0] = __expf(s[nt][0] - mn0);
            s[nt][1] = __expf(s[nt][1] - mn0);
            s[nt][2] = __expf(s[nt][2] - mn1);
            s[nt][3] = __expf(s[nt][3] - mn1);
            sum0 += s[nt][0] + s[nt][1];
            sum1 += s[nt][2] + s[nt][3];
        }
        l0 = l0 * f0 + sum0;
        l1 = l1 * f1 + sum1;
        #pragma unroll
        for (int nt = 0; nt < 8; nt++) {
            cacc[nt][0] *= f0; cacc[nt][1] *= f0;
            cacc[nt][2] *= f1; cacc[nt][3] *= f1;
        }

        // Store P tile (warp-private, 16 rows x 64 halves, swizzled)
        #pragma unroll
        for (int nt = 0; nt < 8; nt++) {
            const int swzp = ((nt ^ (row & 7)) * 16) + 4 * col;
            *(__half2*)(Pw + row * 128 + swzp) =
                __floats2half2_rn(s[nt][0], s[nt][1]);
            *(__half2*)(Pw + (row + 8) * 128 + swzp) =
                __floats2half2_rn(s[nt][2], s[nt][3]);
        }
        __syncwarp();

        // ctx += P · V
        #pragma unroll
        for (int ks = 0; ks < 4; ks++) {
            const int ck   = ks * 2;
            const int swz0 = ((ck ^ (row & 7)) * 16) + 4 * col;
            const int swz1 = (((ck + 1) ^ (row & 7)) * 16) + 4 * col;
            const char* pp0 = Pw + row * 128;
            const char* pp8 = pp0 + 8 * 128;
            uint32_t a[4];
            a[0] = *(const uint32_t*)(pp0 + swz0);
            a[1] = *(const uint32_t*)(pp8 + swz0);
            a[2] = *(const uint32_t*)(pp0 + swz1);
            a[3] = *(const uint32_t*)(pp8 + swz1);
            uint32_t bfr[8][2];
            #pragma unroll
            for (int nt = 0; nt < 8; nt++) {
                const char* bp = Vsb + (nt * 8 + row) * 128;
                bfr[nt][0] = *(const uint32_t*)(bp + swz0);
                bfr[nt][1] = *(const uint32_t*)(bp + swz1);
            }
            #pragma unroll
            for (int nt = 0; nt < 8; nt++)
                mma_f16(cacc[nt], a, bfr[nt]);
        }
        __syncwarp();
    }

    // Final normalize + write ctx [b][q][h*64+d] (fp16)
    l0 += __shfl_xor_sync(0xffffffffu, l0, 1);
    l0 += __shfl_xor_sync(0xffffffffu, l0, 2);
    l1 += __shfl_xor_sync(0xffffffffu, l1, 1);
    l1 += __shfl_xor_sync(0xffffffffu, l1, 2);
    const float inv0 = 1.0f / l0;
    const float inv1 = 1.0f / l1;

    __half* Cb = ctx + (size_t)b * NSEQ * HDIM + h * DHEAD
               + (size_t)(m0 + warp * 16 + row) * HDIM;
    #pragma unroll
    for (int nt = 0; nt < 8; nt++) {
        const int nb = nt * 8 + 2 * col;
        *(__half2*)(Cb + nb) =
            __floats2half2_rn(cacc[nt][0] * inv0, cacc[nt][1] * inv0);
        *(__half2*)(Cb + 8 * HDIM + nb) =
            __floats2half2_rn(cacc[nt][2] * inv1, cacc[nt][3] * inv1);
    }
}

// ---------------------------------------------------------------------------
// Weight transpose + fp16 convert: dst[n][k] = half(src[k][n]) per layer
// ---------------------------------------------------------------------------
__global__ void transpose_kernel(const float* __restrict__ src,
                                 __half* __restrict__ dst, int R, int C) {
    __shared__ float t[32][33];
    const size_t lo = (size_t)blockIdx.z * R * C;
    const int c0 = blockIdx.x * 32, r0 = blockIdx.y * 32;
    #pragma unroll
    for (int i = 0; i < 32; i += 8)
        t[threadIdx.y + i][threadIdx.x] =
            src[lo + (size_t)(r0 + threadIdx.y + i) * C + c0 + threadIdx.x];
    __syncthreads();
    #pragma unroll
    for (int i = 0; i < 32; i += 8)
        dst[lo + (size_t)(c0 + threadIdx.y + i) * R + r0 + threadIdx.x] =
            __float2half_rn(t[threadIdx.x][threadIdx.y + i]);
}

// ---------------------------------------------------------------------------
// LayerNorm: warp-per-row (8 rows per 256-thread block), float4 loads,
// pure shfl reductions, no __syncthreads. fp16 out via uint2 stores.
// ---------------------------------------------------------------------------
__global__ __launch_bounds__(256)
void ln_kernel(const float* __restrict__ x,
               const float* __restrict__ gs,
               const float* __restrict__ gb,
               __half* __restrict__ y) {
    const int warp = threadIdx.x >> 5;
    const int lane = threadIdx.x & 31;
    const int row  = blockIdx.x * 8 + warp;

    const float4* xr = (const float4*)(x + (size_t)row * HDIM);
    float4 v[4];
    float s = 0.0f;
    #pragma unroll
    for (int j = 0; j < 4; j++) {
        v[j] = xr[j * 32 + lane];
        s += v[j].x + v[j].y + v[j].z + v[j].w;
    }
    #pragma unroll
    for (int o = 16; o; o >>= 1) s += __shfl_xor_sync(0xffffffffu, s, o);
    const float mu = s * (1.0f / HDIM);

    float sq = 0.0f;
    #pragma unroll
    for (int j = 0; j < 4; j++) {
        v[j].x -= mu; v[j].y -= mu; v[j].z -= mu; v[j].w -= mu;
        sq += v[j].x * v[j].x + v[j].y * v[j].y + v[j].z * v[j].z + v[j].w * v[j].w;
    }
    #pragma unroll
    for (int o = 16; o; o >>= 1) sq += __shfl_xor_sync(0xffffffffu, sq, o);
    const float inv = rsqrtf(sq * (1.0f / HDIM) + 1e-5f);

    const float4* gs4 = (const float4*)gs;
    const float4* gb4 = (const float4*)gb;
    uint2* yr = (uint2*)(y + (size_t)row * HDIM);
    #pragma unroll
    for (int j = 0; j < 4; j++) {
        const int idx = j * 32 + lane;
        const float4 g = gs4[idx];
        const float4 bb = gb4[idx];
        const __half2 lo = __floats2half2_rn(v[j].x * inv * g.x + bb.x,
                                             v[j].y * inv * g.y + bb.y);
        const __half2 hi = __floats2half2_rn(v[j].z * inv * g.z + bb.z,
                                             v[j].w * inv * g.w + bb.w);
        uint2 pk;
        pk.x = *(const uint32_t*)&lo;
        pk.y = *(const uint32_t*)&hi;
        yr[idx] = pk;
    }
}

// ---------------------------------------------------------------------------
// Host launcher
// ---------------------------------------------------------------------------
extern "C" void kernel_launch(void* const* d_in, const int* in_sizes, int n_in,
                              void* d_out, int out_size) {
    const float* x_in      = (const float*)d_in[0];
    const float* attn_bias = (const float*)d_in[1];
    const float* ln1_s     = (const float*)d_in[2];
    const float* ln1_b     = (const float*)d_in[3];
    const float* wq        = (const float*)d_in[4];
    const float* bq        = (const float*)d_in[5];
    const float* wk        = (const float*)d_in[6];
    const float* bk        = (const float*)d_in[7];
    const float* wv        = (const float*)d_in[8];
    const float* bv        = (const float*)d_in[9];
    const float* wo        = (const float*)d_in[10];
    const float* bo        = (const float*)d_in[11];
    const float* ln2_s     = (const float*)d_in[12];
    const float* ln2_b     = (const float*)d_in[13];
    const float* w1        = (const float*)d_in[14];
    const float* b1        = (const float*)d_in[15];
    const float* w2        = (const float*)d_in[16];
    const float* b2        = (const float*)d_in[17];

    float* X = (float*)d_out;

    __half *yb, *qb, *kb, *cb, *fb, *vt;
    __half *wqt, *wkt, *wvt, *wot, *w1t, *w2t;
    cudaGetSymbolAddress((void**)&yb, g_y);
    cudaGetSymbolAddress((void**)&qb, g_q);
    cudaGetSymbolAddress((void**)&kb, g_k);
    cudaGetSymbolAddress((void**)&cb, g_ctx);
    cudaGetSymbolAddress((void**)&fb, g_ffn);
    cudaGetSymbolAddress((void**)&vt, g_vt);
    cudaGetSymbolAddress((void**)&wqt, g_wqt);
    cudaGetSymbolAddress((void**)&wkt, g_wkt);
    cudaGetSymbolAddress((void**)&wvt, g_wvt);
    cudaGetSymbolAddress((void**)&wot, g_wot);
    cudaGetSymbolAddress((void**)&w1t, g_w1t);
    cudaGetSymbolAddress((void**)&w2t, g_w2t);

    cudaFuncSetAttribute(tgemm_kernel<2>,
                         cudaFuncAttributeMaxDynamicSharedMemorySize, GSMEM3);
    cudaFuncSetAttribute(tgemm_kernel<3>,
                         cudaFuncAttributeMaxDynamicSharedMemorySize, GSMEM3);
    cudaFuncSetAttribute(qkv_kernel,
                         cudaFuncAttributeMaxDynamicSharedMemorySize, GSMEM3);
    cudaFuncSetAttribute(fattn_kernel,
                         cudaFuncAttributeMaxDynamicSharedMemorySize, FA_SMEM);

    cudaMemcpyAsync(X, x_in, (size_t)MROWS * HDIM * sizeof(float),
                    cudaMemcpyDeviceToDevice);

    // One-time weight transposes (+ fp16 convert)
    {
        const dim3 tb(32, 8);
        const dim3 gHH(HDIM / 32, HDIM / 32, LNUM);
        const dim3 gHF(FDIM / 32, HDIM / 32, LNUM);
        const dim3 gFH(HDIM / 32, FDIM / 32, LNUM);
        transpose_kernel<<<gHH, tb>>>(wq, wqt, HDIM, HDIM);
        transpose_kernel<<<gHH, tb>>>(wk, wkt, HDIM, HDIM);
        transpose_kernel<<<gHH, tb>>>(wv, wvt, HDIM, HDIM);
        transpose_kernel<<<gHH, tb>>>(wo, wot, HDIM, HDIM);
        transpose_kernel<<<gHF, tb>>>(w1, w1t, HDIM, FDIM);
        transpose_kernel<<<gFH, tb>>>(w2, w2t, FDIM, HDIM);
    }

    const dim3 gB(256);
    const dim3 tG(128);
    const dim3 gLN(MROWS / 8);                   // 1024 blocks, warp-per-row
    const dim3 gQKV(12, MROWS / 128);            // (12, 64)
    const dim3 gProj(HDIM / 128, MROWS / 128);   // (4, 64)
    const dim3 gFfn1(FDIM / 128, MROWS / 128);   // (16, 64)
    const dim3 gFA(NSEQ / 128, NBH);             // (2, 256)

    for (int l = 0; l < LNUM; l++) {
        const __half* wqt_l = wqt + (size_t)l * HDIM * HDIM;
        const __half* wkt_l = wkt + (size_t)l * HDIM * HDIM;
        const __half* wvt_l = wvt + (size_t)l * HDIM * HDIM;
        const __half* wot_l = wot + (size_t)l * HDIM * HDIM;
        const __half* w1t_l = w1t + (size_t)l * HDIM * FDIM;
        const __half* w2t_l = w2t + (size_t)l * FDIM * HDIM;

        // --- attention block ---
        ln_kernel<<<gLN, gB>>>(X, ln1_s + l * HDIM, ln1_b + l * HDIM, yb);
        qkv_kernel<<<gQKV, tG, GSMEM3>>>(yb, wqt_l, wkt_l, wvt_l,
                                         bq + l * HDIM, bk + l * HDIM, bv + l * HDIM,
                                         qb, kb, vt);
        fattn_kernel<<<gFA, gB, FA_SMEM>>>(qb, kb, vt, attn_bias, cb);
        tgemm_kernel<3><<<gProj, tG, GSMEM3>>>(cb, wot_l, bo + l * HDIM, X,
                                               HDIM, HDIM);

        // --- FFN block ---
        ln_kernel<<<gLN, gB>>>(X, ln2_s + l * HDIM, ln2_b + l * HDIM, yb);
        tgemm_kernel<2><<<gFfn1, tG, GSMEM3>>>(yb, w1t_l, b1 + l * FDIM, fb,
                                               FDIM, HDIM);
        tgemm_kernel<3><<<gProj, tG, GSMEM3>>>(fb, w2t_l, b2 + l * HDIM, X,
                                               HDIM, FDIM);
    }
}

// round 14
// speedup vs baseline: 1.3619x; 1.2489x over previous
#include <cuda_runtime.h>
#include <cuda_fp16.h>
#include <math.h>
#include <stdint.h>

// Problem constants
#define BSZ    32
#define NSEQ   256
#define HDIM   512
#define NHEADS 8
#define DHEAD  64
#define FDIM   2048
#define LNUM   8
#define MROWS  (BSZ * NSEQ)   // 8192
#define NBH    (BSZ * NHEADS) // 256

// ---------------------------------------------------------------------------
// Scratch (static device globals; no runtime allocation allowed)
// ---------------------------------------------------------------------------
__device__ __half g_y  [MROWS * HDIM];
__device__ __half g_q  [MROWS * HDIM];
__device__ __half g_k  [MROWS * HDIM];
__device__ __half g_ctx[MROWS * HDIM];
__device__ __half g_ffn[MROWS * FDIM];
__device__ __half g_vt [NBH * DHEAD * NSEQ];    // per-head transposed V
// Transposed weights: Wt[n][k] = half(W[k][n])
__device__ __half g_wqt[LNUM * HDIM * HDIM];
__device__ __half g_wkt[LNUM * HDIM * HDIM];
__device__ __half g_wvt[LNUM * HDIM * HDIM];
__device__ __half g_wot[LNUM * HDIM * HDIM];
__device__ __half g_w1t[LNUM * HDIM * FDIM];
__device__ __half g_w2t[LNUM * FDIM * HDIM];

// ---------------------------------------------------------------------------
// Common helpers
// ---------------------------------------------------------------------------
__device__ __forceinline__ uint32_t smem_u32(const void* p) {
    uint32_t a;
    asm("{ .reg .u64 t; cvta.to.shared.u64 t, %1; cvt.u32.u64 %0, t; }"
        : "=r"(a) : "l"(p));
    return a;
}

__device__ __forceinline__ void cp_async16(void* dst, const void* src) {
    uint32_t d;
    asm("{ .reg .u64 t; cvta.to.shared.u64 t, %1; cvt.u32.u64 %0, t; }"
        : "=r"(d) : "l"(dst));
    asm volatile("cp.async.cg.shared.global [%0], [%1], 16;" :: "r"(d), "l"(src));
}

#define CP_COMMIT() asm volatile("cp.async.commit_group;" ::: "memory")
#define CP_WAIT(n)  asm volatile("cp.async.wait_group %0;" :: "n"(n) : "memory")

// fp16 MMA m16n8k16, fp32 accumulate (legacy path)
__device__ __forceinline__ void mma_f16(float* d, const uint32_t* a, const uint32_t* b) {
    asm volatile(
        "mma.sync.aligned.m16n8k16.row.col.f32.f16.f16.f32 "
        "{%0,%1,%2,%3}, {%4,%5,%6,%7}, {%8,%9}, {%0,%1,%2,%3};"
        : "+f"(d[0]), "+f"(d[1]), "+f"(d[2]), "+f"(d[3])
        : "r"(a[0]), "r"(a[1]), "r"(a[2]), "r"(a[3]), "r"(b[0]), "r"(b[1]));
}

// ---------------------------------------------------------------------------
// fp16 tile loader: 128 rows x 64 halves (128 B/row); swizzle IS SW128:
// chunk ck of row r lands at r*128 + ((ck ^ (r&7)) * 16)
// ---------------------------------------------------------------------------
__device__ __forceinline__ void load_tile128h(const __half* __restrict__ base, int lda,
                                              int c, char* sdst, int tid) {
    const __half* p = base + c * 64;
    #pragma unroll
    for (int i = 0; i < 8; i++) {
        const int id  = tid + i * 128;
        const int row = id >> 3;
        const int ck  = id & 7;
        const int off = row * 128 + ((ck ^ (row & 7)) * 16);
        cp_async16(sdst + off, p + (size_t)row * lda + ck * 8);
    }
}

#define TILE_B    16384                 // 128 x 64 halves
#define STAGE_B   32768
#define GSMEM3    (3 * STAGE_B)         // 98304 (fallback stages)
#define GSMEM_TC  (1024 + 3 * STAGE_B)  // 99328 (header + stages)

// ---------------------------------------------------------------------------
// tcgen05 helpers — compiled ONLY on an sm_103a-feature pass.
// The harness's compute_103 PTX pass never parses these.
// ---------------------------------------------------------------------------
#if defined(__CUDA_ARCH_FEAT_SM103_ALL)
#define HAS_TCGEN05 1

// SMEM descriptor, SW128 K-major (LBO=1, SBO=64), Blackwell version bit
#define SMEM_DESC_BASE ((2ULL << 61) | (1ULL << 46) | (64ULL << 32) | (1ULL << 16))
#define MAKE_DESC(addr) (SMEM_DESC_BASE | ((uint64_t)((addr) >> 4) & 0x3FFF))

// idesc: dtype=F32(1)<<4, atype=F16(0)<<7, btype=F16(0)<<10, N/8<<17, M/16<<24
#define TC_IDESC ((1u << 4) | (16u << 17) | (8u << 24))

__device__ __forceinline__ uint32_t elect_one() {
    uint32_t pred;
    asm volatile(
        "{ .reg .pred p; elect.sync _|p, 0xFFFFFFFF; selp.b32 %0, 1, 0, p; }"
        : "=r"(pred));
    return pred;
}

#define MBAR_INIT(addr, cnt) \
    asm volatile("mbarrier.init.shared.b64 [%0], %1;" :: "r"(addr), "r"(cnt) : "memory")

#define MBAR_WAIT(addr, par) do {                                              \
    uint32_t _m = (addr), _p = (par), _d;                                      \
    asm volatile("{ .reg .pred p; mbarrier.try_wait.parity.acquire.cta.shared::cta.b64 p, [%1], %2; selp.b32 %0, 1, 0, p; }" \
        : "=r"(_d) : "r"(_m), "r"(_p) : "memory");                             \
    if (!_d) {                                                                 \
        asm volatile("{ .reg .pred P1; WL_%=: mbarrier.try_wait.parity.acquire.cta.shared::cta.b64 P1, [%0], %1, 0x989680; @P1 bra.uni WD_%=; bra.uni WL_%=; WD_%=: }" \
            :: "r"(_m), "r"(_p) : "memory");                                   \
    } } while (0)

#define TC_ALLOC(smem_addr, n) \
    asm volatile("tcgen05.alloc.cta_group::1.sync.aligned.shared::cta.b32 [%0], %1;" \
        :: "r"(smem_addr), "r"((uint32_t)(n)) : "memory")
#define TC_DEALLOC(tmem, n) \
    asm volatile("tcgen05.dealloc.cta_group::1.sync.aligned.b32 %0, %1;" :: "r"(tmem), "r"((uint32_t)(n)))
#define TC_RELINQ() \
    asm volatile("tcgen05.relinquish_alloc_permit.cta_group::1.sync.aligned;")
#define TC_COMMIT(mbar) \
    asm volatile("tcgen05.commit.cta_group::1.mbarrier::arrive::one.shared::cluster.b64 [%0];" \
        :: "r"(mbar) : "memory")

__device__ __forceinline__ void tc_mma_f16(uint32_t d_tmem, uint64_t ad, uint64_t bd,
                                           uint32_t idesc, int acc) {
    asm volatile(
        "{\n\t.reg .pred p;\n\t"
        "setp.ne.u32 p, %4, 0;\n\t"
        "tcgen05.mma.cta_group::1.kind::f16 [%0], %1, %2, %3, {%5, %5, %5, %5}, p;\n\t}"
        :: "r"(d_tmem), "l"(ad), "l"(bd), "r"(idesc), "r"(acc), "r"(0u)
        : "memory");
}

#define TC_LD_X32(r, tmem_addr)                                                \
    asm volatile(                                                              \
        "tcgen05.ld.sync.aligned.32x32b.x32.b32 "                              \
        "{%0, %1, %2, %3, %4, %5, %6, %7, "                                    \
        " %8, %9, %10, %11, %12, %13, %14, %15, "                              \
        " %16, %17, %18, %19, %20, %21, %22, %23, "                            \
        " %24, %25, %26, %27, %28, %29, %30, %31}, [%32];"                     \
        : "=r"((r)[0]),  "=r"((r)[1]),  "=r"((r)[2]),  "=r"((r)[3]),           \
          "=r"((r)[4]),  "=r"((r)[5]),  "=r"((r)[6]),  "=r"((r)[7]),           \
          "=r"((r)[8]),  "=r"((r)[9]),  "=r"((r)[10]), "=r"((r)[11]),          \
          "=r"((r)[12]), "=r"((r)[13]), "=r"((r)[14]), "=r"((r)[15]),          \
          "=r"((r)[16]), "=r"((r)[17]), "=r"((r)[18]), "=r"((r)[19]),          \
          "=r"((r)[20]), "=r"((r)[21]), "=r"((r)[22]), "=r"((r)[23]),          \
          "=r"((r)[24]), "=r"((r)[25]), "=r"((r)[26]), "=r"((r)[27]),          \
          "=r"((r)[28]), "=r"((r)[29]), "=r"((r)[30]), "=r"((r)[31])           \
        : "r"(tmem_addr))

#endif  // __CUDA_ARCH_FEAT_SM103_ALL

// ---------------------------------------------------------------------------
// Legacy GEMM core (fallback; round-13 proven schedule — do not touch)
// ---------------------------------------------------------------------------
__device__ __forceinline__ void gemm_main_h(const __half* __restrict__ A, int lda,
                                            const __half* __restrict__ B, int ldb,
                                            int K, char* smem, int tid,
                                            float (&d)[4][8][4]) {
    const int warp   = tid >> 5;
    const int lane   = tid & 31;
    const int warp_m = (warp >> 1) * 64;
    const int warp_n = (warp & 1) * 64;
    const int row    = lane >> 2;
    const int col    = lane & 3;

    #pragma unroll
    for (int mt = 0; mt < 4; mt++)
        #pragma unroll
        for (int nt = 0; nt < 8; nt++)
            #pragma unroll
            for (int j = 0; j < 4; j++) d[mt][nt][j] = 0.0f;

    const int nch = K / 64;
    load_tile128h(A, lda, 0, smem, tid);
    load_tile128h(B, ldb, 0, smem + TILE_B, tid);
    CP_COMMIT();
    load_tile128h(A, lda, 1, smem + STAGE_B, tid);
    load_tile128h(B, ldb, 1, smem + STAGE_B + TILE_B, tid);
    CP_COMMIT();

    for (int c = 0; c < nch; c++) {
        if (c + 1 < nch) CP_WAIT(1);
        else             CP_WAIT(0);
        __syncthreads();

        if (c + 2 < nch) {
            char* st = smem + ((c + 2) % 3) * STAGE_B;
            load_tile128h(A, lda, c + 2, st, tid);
            load_tile128h(B, ldb, c + 2, st + TILE_B, tid);
            CP_COMMIT();
        }

        const char* Asb = smem + (c % 3) * STAGE_B;
        const char* Bsb = Asb + TILE_B;

        #pragma unroll
        for (int ks = 0; ks < 4; ks++) {
            const int ck   = ks * 2;
            const int swz0 = ((ck ^ (row & 7)) * 16) + 4 * col;
            const int swz1 = (((ck + 1) ^ (row & 7)) * 16) + 4 * col;

            uint32_t a[4][4];
            #pragma unroll
            for (int mt = 0; mt < 4; mt++) {
                const char* ap0 = Asb + (warp_m + mt * 16 + row) * 128;
                const char* ap8 = ap0 + 8 * 128;
                a[mt][0] = *(const uint32_t*)(ap0 + swz0);
                a[mt][1] = *(const uint32_t*)(ap8 + swz0);
                a[mt][2] = *(const uint32_t*)(ap0 + swz1);
                a[mt][3] = *(const uint32_t*)(ap8 + swz1);
            }
            uint32_t b[8][2];
            #pragma unroll
            for (int nt = 0; nt < 8; nt++) {
                const char* bp = Bsb + (warp_n + nt * 8 + row) * 128;
                b[nt][0] = *(const uint32_t*)(bp + swz0);
                b[nt][1] = *(const uint32_t*)(bp + swz1);
            }
            #pragma unroll
            for (int mt = 0; mt < 4; mt++)
                #pragma unroll
                for (int nt = 0; nt < 8; nt++)
                    mma_f16(d[mt][nt], a[mt], b[nt]);
        }
    }
}

// ---------------------------------------------------------------------------
// Generic GEMM kernels (fp16 in, weights pre-transposed)
//   EPI 2: half(gelu(acc + bias)) -> half C   EPI 3: fp32 C += acc + bias
// tcgen05 path (if the arch-feature pass exists) or legacy mma fallback.
// ---------------------------------------------------------------------------
template <int EPI>
__global__ __launch_bounds__(128, 2)
void tgemm_kernel(const __half* __restrict__ A, const __half* __restrict__ Bt,
                  const float* __restrict__ bias, void* __restrict__ Cv,
                  int Ncols, int K) {
    extern __shared__ __align__(1024) char smem[];
    const int tid  = threadIdx.x;
    const int warp = tid >> 5;
    const int lane = tid & 31;
    const int m0 = blockIdx.y * 128;
    const int n0 = blockIdx.x * 128;

#if defined(HAS_TCGEN05)
    // ---------------- tcgen05 SS-mode path ----------------
    const uint32_t sbase = smem_u32(smem);
    const uint32_t mb = sbase + 64;
    char* stg = smem + 1024;

    if (warp == 0) { TC_ALLOC(sbase, 128); TC_RELINQ(); }
    if (tid == 0) { MBAR_INIT(mb, 1); MBAR_INIT(mb + 8, 1); MBAR_INIT(mb + 16, 1); }
    __syncthreads();
    uint32_t tmem;
    asm volatile("ld.shared.b32 %0, [%1];" : "=r"(tmem) : "r"(sbase));

    const __half* Ab = A  + (size_t)m0 * K;
    const __half* Bb = Bt + (size_t)n0 * K;
    const int nch = K / 64;

    load_tile128h(Ab, K, 0, stg, tid);
    load_tile128h(Bb, K, 0, stg + TILE_B, tid);
    CP_COMMIT();
    load_tile128h(Ab, K, 1, stg + STAGE_B, tid);
    load_tile128h(Bb, K, 1, stg + STAGE_B + TILE_B, tid);
    CP_COMMIT();

    int ph0 = 0, ph1 = 0, ph2 = 0;
    for (int c = 0; c < nch; c++) {
        const int st = c % 3;
        if (c + 1 < nch) CP_WAIT(1);
        else             CP_WAIT(0);
        __syncthreads();

        if (warp == 0) {
            asm volatile("fence.proxy.async.shared::cta;" ::: "memory");
            if (elect_one()) {
                const uint32_t ab = sbase + 1024 + (uint32_t)(st * STAGE_B);
                const uint64_t ad = MAKE_DESC(ab);
                const uint64_t bd = MAKE_DESC(ab + TILE_B);
                #pragma unroll
                for (int ks = 0; ks < 4; ks++)
                    tc_mma_f16(tmem, ad + ks * 2, bd + ks * 2, TC_IDESC,
                               (c > 0) || (ks > 0));
                TC_COMMIT(mb + st * 8);
            }
        }

        if (c + 2 < nch) {
            const int st2 = (c + 2) % 3;
            if (c >= 1) {   // stage st2 consumed by chunk c-1's MMAs
                if (st2 == 0)      { MBAR_WAIT(mb,      ph0); ph0 ^= 1; }
                else if (st2 == 1) { MBAR_WAIT(mb + 8,  ph1); ph1 ^= 1; }
                else               { MBAR_WAIT(mb + 16, ph2); ph2 ^= 1; }
            }
            load_tile128h(Ab, K, c + 2, stg + st2 * STAGE_B, tid);
            load_tile128h(Bb, K, c + 2, stg + st2 * STAGE_B + TILE_B, tid);
            CP_COMMIT();
        }
    }
    {
        const int stl = (nch - 1) % 3;
        if (stl == 0)      MBAR_WAIT(mb,      ph0);
        else if (stl == 1) MBAR_WAIT(mb + 8,  ph1);
        else               MBAR_WAIT(mb + 16, ph2);
    }
    asm volatile("tcgen05.fence::after_thread_sync;" ::: "memory");

    // Epilogue: warp w owns rows m0 + w*32 + lane (TMEM lane = row)
    const int rrow = m0 + warp * 32 + lane;
    #pragma unroll
    for (int nb = 0; nb < 4; nb++) {
        uint32_t r[32];
        TC_LD_X32(r, tmem + nb * 32);
        asm volatile("tcgen05.wait::ld.sync.aligned;" ::: "memory");
        const int ncol = n0 + nb * 32;
        if (EPI == 2) {
            __half* crow = (__half*)Cv + (size_t)rrow * Ncols + ncol;
            #pragma unroll
            for (int j = 0; j < 32; j += 2) {
                float v0 = __uint_as_float(r[j])     + bias[ncol + j];
                float v1 = __uint_as_float(r[j + 1]) + bias[ncol + j + 1];
                v0 = 0.5f * v0 * (1.0f + erff(v0 * 0.70710678118654752f));
                v1 = 0.5f * v1 * (1.0f + erff(v1 * 0.70710678118654752f));
                *(__half2*)(crow + j) = __floats2half2_rn(v0, v1);
            }
        } else {
            float* crow = (float*)Cv + (size_t)rrow * Ncols + ncol;
            #pragma unroll
            for (int j = 0; j < 32; j += 4) {
                float4 old = *(float4*)(crow + j);
                old.x += __uint_as_float(r[j])     + bias[ncol + j];
                old.y += __uint_as_float(r[j + 1]) + bias[ncol + j + 1];
                old.z += __uint_as_float(r[j + 2]) + bias[ncol + j + 2];
                old.w += __uint_as_float(r[j + 3]) + bias[ncol + j + 3];
                *(float4*)(crow + j) = old;
            }
        }
    }
    asm volatile("tcgen05.fence::before_thread_sync;" ::: "memory");
    __syncthreads();
    if (warp == 0) TC_DEALLOC(tmem, 128);

#else
    // ---------------- legacy mma fallback (round-13 exact) ----------------
    float d[4][8][4];
    gemm_main_h(A + (size_t)m0 * K, K, Bt + (size_t)n0 * K, K, K, smem, tid, d);

    const int warp_m = (warp >> 1) * 64;
    const int warp_n = (warp & 1) * 64;
    const int row = lane >> 2, col = lane & 3;

    #pragma unroll
    for (int nt = 0; nt < 8; nt++) {
        const int nb = n0 + warp_n + nt * 8 + col * 2;
        const float2 bv = *(const float2*)(bias + nb);
        #pragma unroll
        for (int mt = 0; mt < 4; mt++) {
            const int m1 = m0 + warp_m + mt * 16 + row;
            #pragma unroll
            for (int half_i = 0; half_i < 2; half_i++) {
                const int mr = m1 + half_i * 8;
                float v0 = d[mt][nt][half_i * 2 + 0] + bv.x;
                float v1 = d[mt][nt][half_i * 2 + 1] + bv.y;
                if (EPI == 2) {
                    v0 = 0.5f * v0 * (1.0f + erff(v0 * 0.70710678118654752f));
                    v1 = 0.5f * v1 * (1.0f + erff(v1 * 0.70710678118654752f));
                    __half* crow = (__half*)Cv + (size_t)mr * Ncols + nb;
                    *(__half2*)crow = __floats2half2_rn(v0, v1);
                } else {
                    float* crow = (float*)Cv + (size_t)mr * Ncols + nb;
                    const float2 old = *(const float2*)crow;
                    *(float2*)crow = make_float2(v0 + old.x, v1 + old.y);
                }
            }
        }
    }
#endif
}

// ---------------------------------------------------------------------------
// Fused QKV projection (legacy path always): grid.x = 12
// Q: scaled fp16 out.  K: fp16 out.  V: smem-staged transposed write to vt.
// ---------------------------------------------------------------------------
#define VT_STRIDE 144   // halves per staged row (288 B, 16B-aligned)

__global__ __launch_bounds__(128, 2)
void qkv_kernel(const __half* __restrict__ A,
                const __half* __restrict__ wqt, const __half* __restrict__ wkt,
                const __half* __restrict__ wvt,
                const float* __restrict__ bq, const float* __restrict__ bk,
                const float* __restrict__ bv,
                __half* __restrict__ q, __half* __restrict__ k,
                __half* __restrict__ vt) {
    extern __shared__ __align__(1024) char smem[];
    const int tid  = threadIdx.x;
    const int warp = tid >> 5;
    const int lane = tid & 31;
    const int sel = blockIdx.x >> 2;
    const int n0  = (blockIdx.x & 3) * 128;
    const int m0  = blockIdx.y * 128;

    const __half* Bt  = (sel == 0) ? wqt : (sel == 1) ? wkt : wvt;
    const float* bias = (sel == 0) ? bq  : (sel == 1) ? bk  : bv;
    const float scale = (sel == 0) ? 0.125f : 1.0f;

    float d[4][8][4];
    gemm_main_h(A + (size_t)m0 * HDIM, HDIM, Bt + (size_t)n0 * HDIM, HDIM, HDIM,
                smem, tid, d);

    const int warp_m = (warp >> 1) * 64;
    const int warp_n = (warp & 1) * 64;
    const int row = lane >> 2, col = lane & 3;

    if (sel < 2) {
        __half* C = (sel == 0) ? q : k;
        #pragma unroll
        for (int nt = 0; nt < 8; nt++) {
            const int nb = n0 + warp_n + nt * 8 + col * 2;
            const float2 bvv = *(const float2*)(bias + nb);
            #pragma unroll
            for (int mt = 0; mt < 4; mt++) {
                const int m1 = m0 + warp_m + mt * 16 + row;
                #pragma unroll
                for (int half_i = 0; half_i < 2; half_i++) {
                    __half* crow = C + (size_t)(m1 + half_i * 8) * HDIM + nb;
                    const float v0 = (d[mt][nt][half_i * 2 + 0] + bvv.x) * scale;
                    const float v1 = (d[mt][nt][half_i * 2 + 1] + bvv.y) * scale;
                    *(__half2*)crow = __floats2half2_rn(v0, v1);
                }
            }
        }
    } else {
        // V path: stage [n_local][m_local] tile in smem, then coalesced
        // transposed write-out to vt[bh][d][j].
        __syncthreads();
        __half* tp = (__half*)smem;   // [128][VT_STRIDE]
        #pragma unroll
        for (int nt = 0; nt < 8; nt++) {
            const int nl = warp_n + nt * 8 + col * 2;
            const float2 bvv = *(const float2*)(bias + n0 + nl);
            #pragma unroll
            for (int mt = 0; mt < 4; mt++) {
                #pragma unroll
                for (int half_i = 0; half_i < 2; half_i++) {
                    const int ml = warp_m + mt * 16 + row + half_i * 8;
                    tp[nl * VT_STRIDE + ml] =
                        __float2half_rn(d[mt][nt][half_i * 2 + 0] + bvv.x);
                    tp[(nl + 1) * VT_STRIDE + ml] =
                        __float2half_rn(d[mt][nt][half_i * 2 + 1] + bvv.y);
                }
            }
        }
        __syncthreads();

        const int bb = m0 >> 8;
        const int j0 = m0 & 255;
        const int chunk = tid & 15;
        const int rsub  = tid >> 4;
        #pragma unroll
        for (int it = 0; it < 16; it++) {
            const int nl = it * 8 + rsub;
            const int h  = (n0 + nl) >> 6;
            const int dd = (n0 + nl) & 63;
            const uint4 val = *(const uint4*)(tp + nl * VT_STRIDE + chunk * 8);
            __half* dst = vt + ((size_t)(bb * 8 + h) * DHEAD + dd) * NSEQ + j0;
            *(uint4*)(dst + chunk * 8) = val;
        }
    }
}

// ---------------------------------------------------------------------------
// Fused flash attention (fp16 operands): ctx = softmax(Q·K^T + bias) · V
// ---------------------------------------------------------------------------
#define FA_STAGE 16384
#define FA_SMEM  (16384 + 2 * FA_STAGE)   // 49152

__device__ __forceinline__ void load_kv_h(const __half* __restrict__ Kb,
                                          const __half* __restrict__ Vb,
                                          int j0, char* st, int tid) {
    char* Ks = st;
    char* Vs = st + 8192;
    #pragma unroll
    for (int i = 0; i < 2; i++) {
        const int id = tid + i * 256;
        const int r  = id >> 3;
        const int ck = id & 7;
        const int off = r * 128 + ((ck ^ (r & 7)) * 16);
        cp_async16(Ks + off, Kb + (size_t)(j0 + r) * HDIM + ck * 8);
        cp_async16(Vs + off, Vb + (size_t)r * NSEQ + j0 + ck * 8);
    }
}

__global__ __launch_bounds__(256, 2)
void fattn_kernel(const __half* __restrict__ q, const __half* __restrict__ k,
                  const __half* __restrict__ vt, const float* __restrict__ attn_bias,
                  __half* __restrict__ ctx) {
    extern __shared__ __align__(16) char smem[];
    char* QP    = smem;
    char* stage = smem + 16384;

    const int tid  = threadIdx.x;
    const int warp = tid >> 5;
    const int lane = tid & 31;
    const int row  = lane >> 2;
    const int col  = lane & 3;
    const int bh = blockIdx.y;
    const int b  = bh >> 3, h = bh & 7;
    const int m0 = blockIdx.x * 128;

    const __half* Qb = q  + (size_t)b * NSEQ * HDIM + (size_t)m0 * HDIM + h * DHEAD;
    const __half* Kb = k  + (size_t)b * NSEQ * HDIM + h * DHEAD;
    const __half* Vb = vt + (size_t)bh * DHEAD * NSEQ;

    #pragma unroll
    for (int i = 0; i < 4; i++) {
        const int id = tid + i * 256;
        const int r  = id >> 3;
        const int ck = id & 7;
        const int off = r * 128 + ((ck ^ (r & 7)) * 16);
        cp_async16(QP + off, Qb + (size_t)r * HDIM + ck * 8);
    }
    CP_COMMIT();
    load_kv_h(Kb, Vb, 0, stage, tid);
    CP_COMMIT();

    CP_WAIT(1);
    __syncthreads();
    uint32_t aq[4][4];
    #pragma unroll
    for (int ks = 0; ks < 4; ks++) {
        const int ck   = ks * 2;
        const int swz0 = ((ck ^ (row & 7)) * 16) + 4 * col;
        const int swz1 = (((ck + 1) ^ (row & 7)) * 16) + 4 * col;
        const char* ap0 = QP + (warp * 16 + row) * 128;
        const char* ap8 = ap0 + 8 * 128;
        aq[ks][0] = *(const uint32_t*)(ap0 + swz0);
        aq[ks][1] = *(const uint32_t*)(ap8 + swz0);
        aq[ks][2] = *(const uint32_t*)(ap0 + swz1);
        aq[ks][3] = *(const uint32_t*)(ap8 + swz1);
    }
    __syncthreads();

    float m0r = -1e30f, m1r = -1e30f, l0 = 0.0f, l1 = 0.0f;
    float cacc[8][4];
    #pragma unroll
    for (int nt = 0; nt < 8; nt++)
        #pragma unroll
        for (int j = 0; j < 4; j++) cacc[nt][j] = 0.0f;

    const float* bias_b = attn_bias + (size_t)bh * NSEQ * NSEQ
                        + (size_t)(m0 + warp * 16 + row) * NSEQ;
    char* Pw = QP + warp * 2048;

    for (int c = 0; c < 4; c++) {
        CP_WAIT(0);
        __syncthreads();
        if (c < 3) {
            load_kv_h(Kb, Vb, (c + 1) * 64, stage + ((c + 1) & 1) * FA_STAGE, tid);
            CP_COMMIT();
        }

        const char* Ksb = stage + (c & 1) * FA_STAGE;
        const char* Vsb = Ksb + 8192;

        float s[8][4];
        #pragma unroll
        for (int nt = 0; nt < 8; nt++)
            #pragma unroll
            for (int j = 0; j < 4; j++) s[nt][j] = 0.0f;

        #pragma unroll
        for (int ks = 0; ks < 4; ks++) {
            const int ck   = ks * 2;
            const int swz0 = ((ck ^ (row & 7)) * 16) + 4 * col;
            const int swz1 = (((ck + 1) ^ (row & 7)) * 16) + 4 * col;
            uint32_t bfr[8][2];
            #pragma unroll
            for (int nt = 0; nt < 8; nt++) {
                const char* bp = Ksb + (nt * 8 + row) * 128;
                bfr[nt][0] = *(const uint32_t*)(bp + swz0);
                bfr[nt][1] = *(const uint32_t*)(bp + swz1);
            }
            #pragma unroll
            for (int nt = 0; nt < 8; nt++)
                mma_f16(s[nt], aq[ks], bfr[nt]);
        }

        float mx0 = -1e30f, mx1 = -1e30f;
        #pragma unroll
        for (int nt = 0; nt < 8; nt++) {
            const float* bp = bias_b + c * 64 + nt * 8 + 2 * col;
            const float2 b0 = *(const float2*)bp;
            const float2 b1 = *(const float2*)(bp + 8 * NSEQ);
            s[nt][0] += b0.x; s[nt][1] += b0.y;
            s[nt][2] += b1.x; s[nt][3] += b1.y;
            mx0 = fmaxf(mx0, fmaxf(s[nt][0], s[nt][1]));
            mx1 = fmaxf(mx1, fmaxf(s[nt][2], s[nt][3]));
        }
        mx0 = fmaxf(mx0, __shfl_xor_sync(0xffffffffu, mx0, 1));
        mx0 = fmaxf(mx0, __shfl_xor_sync(0xffffffffu, mx0, 2));
        mx1 = fmaxf(mx1, __shfl_xor_sync(0xffffffffu, mx1, 1));
        mx1 = fmaxf(mx1, __shfl_xor_sync(0xffffffffu, mx1, 2));

        const float mn0 = fmaxf(m0r, mx0);
        const float mn1 = fmaxf(m1r, mx1);
        const float f0 = __expf(m0r - mn0);
        const float f1 = __expf(m1r - mn1);
        m0r = mn0; m1r = mn1;

        float sum0 = 0.0f, sum1 = 0.0f;
        #pragma unroll
        for (int nt = 0; nt < 8; nt++) {
            s[nt][0] = __expf(s[nt][0] - mn0);
            s[nt][1] = __expf(s[nt][1] - mn0);
            s[nt][2] = __expf(s[nt][2] - mn1);
            s[nt][3] = __expf(s[nt][3] - mn1);
            sum0 += s[nt][0] + s[nt][1];
            sum1 += s[nt][2] + s[nt][3];
        }
        l0 = l0 * f0 + sum0;
        l1 = l1 * f1 + sum1;
        #pragma unroll
        for (int nt = 0; nt < 8; nt++) {
            cacc[nt][0] *= f0; cacc[nt][1] *= f0;
            cacc[nt][2] *= f1; cacc[nt][3] *= f1;
        }

        #pragma unroll
        for (int nt = 0; nt < 8; nt++) {
            const int swzp = ((nt ^ (row & 7)) * 16) + 4 * col;
            *(__half2*)(Pw + row * 128 + swzp) =
                __floats2half2_rn(s[nt][0], s[nt][1]);
            *(__half2*)(Pw + (row + 8) * 128 + swzp) =
                __floats2half2_rn(s[nt][2], s[nt][3]);
        }
        __syncwarp();

        #pragma unroll
        for (int ks = 0; ks < 4; ks++) {
            const int ck   = ks * 2;
            const int swz0 = ((ck ^ (row & 7)) * 16) + 4 * col;
            const int swz1 = (((ck + 1) ^ (row & 7)) * 16) + 4 * col;
            const char* pp0 = Pw + row * 128;
            const char* pp8 = pp0 + 8 * 128;
            uint32_t a[4];
            a[0] = *(const uint32_t*)(pp0 + swz0);
            a[1] = *(const uint32_t*)(pp8 + swz0);
            a[2] = *(const uint32_t*)(pp0 + swz1);
            a[3] = *(const uint32_t*)(pp8 + swz1);
            uint32_t bfr[8][2];
            #pragma unroll
            for (int nt = 0; nt < 8; nt++) {
                const char* bp = Vsb + (nt * 8 + row) * 128;
                bfr[nt][0] = *(const uint32_t*)(bp + swz0);
                bfr[nt][1] = *(const uint32_t*)(bp + swz1);
            }
            #pragma unroll
            for (int nt = 0; nt < 8; nt++)
                mma_f16(cacc[nt], a, bfr[nt]);
        }
        __syncwarp();
    }

    l0 += __shfl_xor_sync(0xffffffffu, l0, 1);
    l0 += __shfl_xor_sync(0xffffffffu, l0, 2);
    l1 += __shfl_xor_sync(0xffffffffu, l1, 1);
    l1 += __shfl_xor_sync(0xffffffffu, l1, 2);
    const float inv0 = 1.0f / l0;
    const float inv1 = 1.0f / l1;

    __half* Cb = ctx + (size_t)b * NSEQ * HDIM + h * DHEAD
               + (size_t)(m0 + warp * 16 + row) * HDIM;
    #pragma unroll
    for (int nt = 0; nt < 8; nt++) {
        const int nb = nt * 8 + 2 * col;
        *(__half2*)(Cb + nb) =
            __floats2half2_rn(cacc[nt][0] * inv0, cacc[nt][1] * inv0);
        *(__half2*)(Cb + 8 * HDIM + nb) =
            __floats2half2_rn(cacc[nt][2] * inv1, cacc[nt][3] * inv1);
    }
}

// ---------------------------------------------------------------------------
// Weight transpose + fp16 convert: dst[n][k] = half(src[k][n]) per layer
// ---------------------------------------------------------------------------
__global__ void transpose_kernel(const float* __restrict__ src,
                                 __half* __restrict__ dst, int R, int C) {
    __shared__ float t[32][33];
    const size_t lo = (size_t)blockIdx.z * R * C;
    const int c0 = blockIdx.x * 32, r0 = blockIdx.y * 32;
    #pragma unroll
    for (int i = 0; i < 32; i += 8)
        t[threadIdx.y + i][threadIdx.x] =
            src[lo + (size_t)(r0 + threadIdx.y + i) * C + c0 + threadIdx.x];
    __syncthreads();
    #pragma unroll
    for (int i = 0; i < 32; i += 8)
        dst[lo + (size_t)(c0 + threadIdx.y + i) * R + r0 + threadIdx.x] =
            __float2half_rn(t[threadIdx.x][threadIdx.y + i]);
}

// ---------------------------------------------------------------------------
// LayerNorm: warp-per-row, float4 loads, shfl reductions, fp16 out
// ---------------------------------------------------------------------------
__global__ __launch_bounds__(256)
void ln_kernel(const float* __restrict__ x,
               const float* __restrict__ gs,
               const float* __restrict__ gb,
               __half* __restrict__ y) {
    const int warp = threadIdx.x >> 5;
    const int lane = threadIdx.x & 31;
    const int row  = blockIdx.x * 8 + warp;

    const float4* xr = (const float4*)(x + (size_t)row * HDIM);
    float4 v[4];
    float s = 0.0f;
    #pragma unroll
    for (int j = 0; j < 4; j++) {
        v[j] = xr[j * 32 + lane];
        s += v[j].x + v[j].y + v[j].z + v[j].w;
    }
    #pragma unroll
    for (int o = 16; o; o >>= 1) s += __shfl_xor_sync(0xffffffffu, s, o);
    const float mu = s * (1.0f / HDIM);

    float sq = 0.0f;
    #pragma unroll
    for (int j = 0; j < 4; j++) {
        v[j].x -= mu; v[j].y -= mu; v[j].z -= mu; v[j].w -= mu;
        sq += v[j].x * v[j].x + v[j].y * v[j].y + v[j].z * v[j].z + v[j].w * v[j].w;
    }
    #pragma unroll
    for (int o = 16; o; o >>= 1) sq += __shfl_xor_sync(0xffffffffu, sq, o);
    const float inv = rsqrtf(sq * (1.0f / HDIM) + 1e-5f);

    const float4* gs4 = (const float4*)gs;
    const float4* gb4 = (const float4*)gb;
    uint2* yr = (uint2*)(y + (size_t)row * HDIM);
    #pragma unroll
    for (int j = 0; j < 4; j++) {
        const int idx = j * 32 + lane;
        const float4 g = gs4[idx];
        const float4 bb = gb4[idx];
        const __half2 lo = __floats2half2_rn(v[j].x * inv * g.x + bb.x,
                                             v[j].y * inv * g.y + bb.y);
        const __half2 hi = __floats2half2_rn(v[j].z * inv * g.z + bb.z,
                                             v[j].w * inv * g.w + bb.w);
        uint2 pk;
        pk.x = *(const uint32_t*)&lo;
        pk.y = *(const uint32_t*)&hi;
        yr[idx] = pk;
    }
}

// ---------------------------------------------------------------------------
// Host launcher
// ---------------------------------------------------------------------------
extern "C" void kernel_launch(void* const* d_in, const int* in_sizes, int n_in,
                              void* d_out, int out_size) {
    const float* x_in      = (const float*)d_in[0];
    const float* attn_bias = (const float*)d_in[1];
    const float* ln1_s     = (const float*)d_in[2];
    const float* ln1_b     = (const float*)d_in[3];
    const float* wq        = (const float*)d_in[4];
    const float* bq        = (const float*)d_in[5];
    const float* wk        = (const float*)d_in[6];
    const float* bk        = (const float*)d_in[7];
    const float* wv        = (const float*)d_in[8];
    const float* bv        = (const float*)d_in[9];
    const float* wo        = (const float*)d_in[10];
    const float* bo        = (const float*)d_in[11];
    const float* ln2_s     = (const float*)d_in[12];
    const float* ln2_b     = (const float*)d_in[13];
    const float* w1        = (const float*)d_in[14];
    const float* b1        = (const float*)d_in[15];
    const float* w2        = (const float*)d_in[16];
    const float* b2        = (const float*)d_in[17];

    float* X = (float*)d_out;

    __half *yb, *qb, *kb, *cb, *fb, *vt;
    __half *wqt, *wkt, *wvt, *wot, *w1t, *w2t;
    cudaGetSymbolAddress((void**)&yb, g_y);
    cudaGetSymbolAddress((void**)&qb, g_q);
    cudaGetSymbolAddress((void**)&kb, g_k);
    cudaGetSymbolAddress((void**)&cb, g_ctx);
    cudaGetSymbolAddress((void**)&fb, g_ffn);
    cudaGetSymbolAddress((void**)&vt, g_vt);
    cudaGetSymbolAddress((void**)&wqt, g_wqt);
    cudaGetSymbolAddress((void**)&wkt, g_wkt);
    cudaGetSymbolAddress((void**)&wvt, g_wvt);
    cudaGetSymbolAddress((void**)&wot, g_wot);
    cudaGetSymbolAddress((void**)&w1t, g_w1t);
    cudaGetSymbolAddress((void**)&w2t, g_w2t);

    cudaFuncSetAttribute(tgemm_kernel<2>,
                         cudaFuncAttributeMaxDynamicSharedMemorySize, GSMEM_TC);
    cudaFuncSetAttribute(tgemm_kernel<3>,
                         cudaFuncAttributeMaxDynamicSharedMemorySize, GSMEM_TC);
    cudaFuncSetAttribute(qkv_kernel,
                         cudaFuncAttributeMaxDynamicSharedMemorySize, GSMEM3);
    cudaFuncSetAttribute(fattn_kernel,
                         cudaFuncAttributeMaxDynamicSharedMemorySize, FA_SMEM);

    cudaMemcpyAsync(X, x_in, (size_t)MROWS * HDIM * sizeof(float),
                    cudaMemcpyDeviceToDevice);

    // One-time weight transposes (+ fp16 convert)
    {
        const dim3 tb(32, 8);
        const dim3 gHH(HDIM / 32, HDIM / 32, LNUM);
        const dim3 gHF(FDIM / 32, HDIM / 32, LNUM);
        const dim3 gFH(HDIM / 32, FDIM / 32, LNUM);
        transpose_kernel<<<gHH, tb>>>(wq, wqt, HDIM, HDIM);
        transpose_kernel<<<gHH, tb>>>(wk, wkt, HDIM, HDIM);
        transpose_kernel<<<gHH, tb>>>(wv, wvt, HDIM, HDIM);
        transpose_kernel<<<gHH, tb>>>(wo, wot, HDIM, HDIM);
        transpose_kernel<<<gHF, tb>>>(w1, w1t, HDIM, FDIM);
        transpose_kernel<<<gFH, tb>>>(w2, w2t, FDIM, HDIM);
    }

    const dim3 gB(256);
    const dim3 tG(128);
    const dim3 gLN(MROWS / 8);                   // 1024 blocks, warp-per-row
    const dim3 gQKV(12, MROWS / 128);            // (12, 64)
    const dim3 gProj(HDIM / 128, MROWS / 128);   // (4, 64)
    const dim3 gFfn1(FDIM / 128, MROWS / 128);   // (16, 64)
    const dim3 gFA(NSEQ / 128, NBH);             // (2, 256)

    for (int l = 0; l < LNUM; l++) {
        const __half* wqt_l = wqt + (size_t)l * HDIM * HDIM;
        const __half* wkt_l = wkt + (size_t)l * HDIM * HDIM;
        const __half* wvt_l = wvt + (size_t)l * HDIM * HDIM;
        const __half* wot_l = wot + (size_t)l * HDIM * HDIM;
        const __half* w1t_l = w1t + (size_t)l * HDIM * FDIM;
        const __half* w2t_l = w2t + (size_t)l * FDIM * HDIM;

        // --- attention block ---
        ln_kernel<<<gLN, gB>>>(X, ln1_s + l * HDIM, ln1_b + l * HDIM, yb);
        qkv_kernel<<<gQKV, tG, GSMEM3>>>(yb, wqt_l, wkt_l, wvt_l,
                                         bq + l * HDIM, bk + l * HDIM, bv + l * HDIM,
                                         qb, kb, vt);
        fattn_kernel<<<gFA, gB, FA_SMEM>>>(qb, kb, vt, attn_bias, cb);
        tgemm_kernel<3><<<gProj, tG, GSMEM_TC>>>(cb, wot_l, bo + l * HDIM, X,
                                                 HDIM, HDIM);

        // --- FFN block ---
        ln_kernel<<<gLN, gB>>>(X, ln2_s + l * HDIM, ln2_b + l * HDIM, yb);
        tgemm_kernel<2><<<gFfn1, tG, GSMEM_TC>>>(yb, w1t_l, b1 + l * FDIM, fb,
                                                 FDIM, HDIM);
        tgemm_kernel<3><<<gProj, tG, GSMEM_TC>>>(fb, w2t_l, b2 + l * HDIM, X,
                                                 HDIM, FDIM);
    }
}

// round 15
// speedup vs baseline: 1.3821x; 1.0148x over previous
#include <cuda_runtime.h>
#include <cuda_fp16.h>
#include <math.h>
#include <stdint.h>

// Problem constants
#define BSZ    32
#define NSEQ   256
#define HDIM   512
#define NHEADS 8
#define DHEAD  64
#define FDIM   2048
#define LNUM   8
#define MROWS  (BSZ * NSEQ)   // 8192
#define NBH    (BSZ * NHEADS) // 256

// ---------------------------------------------------------------------------
// Scratch (static device globals; no runtime allocation allowed)
// ---------------------------------------------------------------------------
__device__ __half g_y  [MROWS * HDIM];
__device__ __half g_q  [MROWS * HDIM];
__device__ __half g_k  [MROWS * HDIM];
__device__ __half g_ctx[MROWS * HDIM];
__device__ __half g_ffn[MROWS * FDIM];
__device__ __half g_vt [NBH * DHEAD * NSEQ];    // per-head transposed V
// Transposed weights: Wt[n][k] = half(W[k][n])
__device__ __half g_wqt[LNUM * HDIM * HDIM];
__device__ __half g_wkt[LNUM * HDIM * HDIM];
__device__ __half g_wvt[LNUM * HDIM * HDIM];
__device__ __half g_wot[LNUM * HDIM * HDIM];
__device__ __half g_w1t[LNUM * HDIM * FDIM];
__device__ __half g_w2t[LNUM * FDIM * HDIM];

// ---------------------------------------------------------------------------
// Common helpers
// ---------------------------------------------------------------------------
__device__ __forceinline__ uint32_t smem_u32(const void* p) {
    uint32_t a;
    asm("{ .reg .u64 t; cvta.to.shared.u64 t, %1; cvt.u32.u64 %0, t; }"
        : "=r"(a) : "l"(p));
    return a;
}

__device__ __forceinline__ void cp_async16(void* dst, const void* src) {
    uint32_t d;
    asm("{ .reg .u64 t; cvta.to.shared.u64 t, %1; cvt.u32.u64 %0, t; }"
        : "=r"(d) : "l"(dst));
    asm volatile("cp.async.cg.shared.global [%0], [%1], 16;" :: "r"(d), "l"(src));
}

#define CP_COMMIT() asm volatile("cp.async.commit_group;" ::: "memory")
#define CP_WAIT(n)  asm volatile("cp.async.wait_group %0;" :: "n"(n) : "memory")

// fp16 MMA m16n8k16, fp32 accumulate (legacy path)
__device__ __forceinline__ void mma_f16(float* d, const uint32_t* a, const uint32_t* b) {
    asm volatile(
        "mma.sync.aligned.m16n8k16.row.col.f32.f16.f16.f32 "
        "{%0,%1,%2,%3}, {%4,%5,%6,%7}, {%8,%9}, {%0,%1,%2,%3};"
        : "+f"(d[0]), "+f"(d[1]), "+f"(d[2]), "+f"(d[3])
        : "r"(a[0]), "r"(a[1]), "r"(a[2]), "r"(a[3]), "r"(b[0]), "r"(b[1]));
}

// ---------------------------------------------------------------------------
// fp16 tile loader: 128 rows x 64 halves (128 B/row); swizzle IS SW128:
// chunk ck of row r lands at r*128 + ((ck ^ (r&7)) * 16)
// ---------------------------------------------------------------------------
__device__ __forceinline__ void load_tile128h(const __half* __restrict__ base, int lda,
                                              int c, char* sdst, int tid) {
    const __half* p = base + c * 64;
    #pragma unroll
    for (int i = 0; i < 8; i++) {
        const int id  = tid + i * 128;
        const int row = id >> 3;
        const int ck  = id & 7;
        const int off = row * 128 + ((ck ^ (row & 7)) * 16);
        cp_async16(sdst + off, p + (size_t)row * lda + ck * 8);
    }
}

#define TILE_B    16384                 // 128 x 64 halves
#define STAGE_B   32768
#define GSMEM3    (3 * STAGE_B)         // 98304 (fallback stages)
#define GSMEM_TC  (1024 + 3 * STAGE_B)  // 99328 (header + stages)

// ---------------------------------------------------------------------------
// tcgen05 helpers — compiled ONLY on the sm_103a-feature pass.
// ---------------------------------------------------------------------------
#if defined(__CUDA_ARCH_FEAT_SM103_ALL)
#define HAS_TCGEN05 1

// SMEM descriptor, SW128 K-major (LBO=1, SBO=64), Blackwell version bit
#define SMEM_DESC_BASE ((2ULL << 61) | (1ULL << 46) | (64ULL << 32) | (1ULL << 16))
#define MAKE_DESC(addr) (SMEM_DESC_BASE | ((uint64_t)((addr) >> 4) & 0x3FFF))

// idesc: dtype=F32(1)<<4, atype=F16(0)<<7, btype=F16(0)<<10, N/8<<17, M/16<<24
#define TC_IDESC ((1u << 4) | (16u << 17) | (8u << 24))

__device__ __forceinline__ uint32_t elect_one() {
    uint32_t pred;
    asm volatile(
        "{ .reg .pred p; elect.sync _|p, 0xFFFFFFFF; selp.b32 %0, 1, 0, p; }"
        : "=r"(pred));
    return pred;
}

#define MBAR_INIT(addr, cnt) \
    asm volatile("mbarrier.init.shared.b64 [%0], %1;" :: "r"(addr), "r"(cnt) : "memory")

#define MBAR_WAIT(addr, par) do {                                              \
    uint32_t _m = (addr), _p = (par), _d;                                      \
    asm volatile("{ .reg .pred p; mbarrier.try_wait.parity.acquire.cta.shared::cta.b64 p, [%1], %2; selp.b32 %0, 1, 0, p; }" \
        : "=r"(_d) : "r"(_m), "r"(_p) : "memory");                             \
    if (!_d) {                                                                 \
        asm volatile("{ .reg .pred P1; WL_%=: mbarrier.try_wait.parity.acquire.cta.shared::cta.b64 P1, [%0], %1, 0x989680; @P1 bra.uni WD_%=; bra.uni WL_%=; WD_%=: }" \
            :: "r"(_m), "r"(_p) : "memory");                                   \
    } } while (0)

#define TC_ALLOC(smem_addr, n) \
    asm volatile("tcgen05.alloc.cta_group::1.sync.aligned.shared::cta.b32 [%0], %1;" \
        :: "r"(smem_addr), "r"((uint32_t)(n)) : "memory")
#define TC_DEALLOC(tmem, n) \
    asm volatile("tcgen05.dealloc.cta_group::1.sync.aligned.b32 %0, %1;" :: "r"(tmem), "r"((uint32_t)(n)))
#define TC_RELINQ() \
    asm volatile("tcgen05.relinquish_alloc_permit.cta_group::1.sync.aligned;")
#define TC_COMMIT(mbar) \
    asm volatile("tcgen05.commit.cta_group::1.mbarrier::arrive::one.shared::cluster.b64 [%0];" \
        :: "r"(mbar) : "memory")

__device__ __forceinline__ void tc_mma_f16(uint32_t d_tmem, uint64_t ad, uint64_t bd,
                                           uint32_t idesc, int acc) {
    asm volatile(
        "{\n\t.reg .pred p;\n\t"
        "setp.ne.u32 p, %4, 0;\n\t"
        "tcgen05.mma.cta_group::1.kind::f16 [%0], %1, %2, %3, {%5, %5, %5, %5}, p;\n\t}"
        :: "r"(d_tmem), "l"(ad), "l"(bd), "r"(idesc), "r"(acc), "r"(0u)
        : "memory");
}

#define TC_LD_X32(r, tmem_addr)                                                \
    asm volatile(                                                              \
        "tcgen05.ld.sync.aligned.32x32b.x32.b32 "                              \
        "{%0, %1, %2, %3, %4, %5, %6, %7, "                                    \
        " %8, %9, %10, %11, %12, %13, %14, %15, "                              \
        " %16, %17, %18, %19, %20, %21, %22, %23, "                            \
        " %24, %25, %26, %27, %28, %29, %30, %31}, [%32];"                     \
        : "=r"((r)[0]),  "=r"((r)[1]),  "=r"((r)[2]),  "=r"((r)[3]),           \
          "=r"((r)[4]),  "=r"((r)[5]),  "=r"((r)[6]),  "=r"((r)[7]),           \
          "=r"((r)[8]),  "=r"((r)[9]),  "=r"((r)[10]), "=r"((r)[11]),          \
          "=r"((r)[12]), "=r"((r)[13]), "=r"((r)[14]), "=r"((r)[15]),          \
          "=r"((r)[16]), "=r"((r)[17]), "=r"((r)[18]), "=r"((r)[19]),          \
          "=r"((r)[20]), "=r"((r)[21]), "=r"((r)[22]), "=r"((r)[23]),          \
          "=r"((r)[24]), "=r"((r)[25]), "=r"((r)[26]), "=r"((r)[27]),          \
          "=r"((r)[28]), "=r"((r)[29]), "=r"((r)[30]), "=r"((r)[31])           \
        : "r"(tmem_addr))

// Shared tcgen05 SS mainloop: accumulates A[128,K] @ B[128,K]^T into TMEM.
// smem layout: [0,64) tmem ptr, [64,1024) mbarriers, [1024, ...) 3 stages.
__device__ __forceinline__ uint32_t tc_gemm_main(const __half* __restrict__ Ab,
                                                 const __half* __restrict__ Bb,
                                                 int K, char* smem, int tid) {
    const int warp = tid >> 5;
    const uint32_t sbase = smem_u32(smem);
    const uint32_t mb = sbase + 64;
    char* stg = smem + 1024;

    if (warp == 0) { TC_ALLOC(sbase, 128); TC_RELINQ(); }
    if (tid == 0) { MBAR_INIT(mb, 1); MBAR_INIT(mb + 8, 1); MBAR_INIT(mb + 16, 1); }
    __syncthreads();
    uint32_t tmem;
    asm volatile("ld.shared.b32 %0, [%1];" : "=r"(tmem) : "r"(sbase));

    const int nch = K / 64;
    load_tile128h(Ab, K, 0, stg, tid);
    load_tile128h(Bb, K, 0, stg + TILE_B, tid);
    CP_COMMIT();
    load_tile128h(Ab, K, 1, stg + STAGE_B, tid);
    load_tile128h(Bb, K, 1, stg + STAGE_B + TILE_B, tid);
    CP_COMMIT();

    int ph0 = 0, ph1 = 0, ph2 = 0;
    for (int c = 0; c < nch; c++) {
        const int st = c % 3;
        if (c + 1 < nch) CP_WAIT(1);
        else             CP_WAIT(0);
        __syncthreads();

        if (warp == 0) {
            asm volatile("fence.proxy.async.shared::cta;" ::: "memory");
            if (elect_one()) {
                const uint32_t ab = sbase + 1024 + (uint32_t)(st * STAGE_B);
                const uint64_t ad = MAKE_DESC(ab);
                const uint64_t bd = MAKE_DESC(ab + TILE_B);
                #pragma unroll
                for (int ks = 0; ks < 4; ks++)
                    tc_mma_f16(tmem, ad + ks * 2, bd + ks * 2, TC_IDESC,
                               (c > 0) || (ks > 0));
                TC_COMMIT(mb + st * 8);
            }
        }

        if (c + 2 < nch) {
            const int st2 = (c + 2) % 3;
            if (c >= 1) {
                if (st2 == 0)      { MBAR_WAIT(mb,      ph0); ph0 ^= 1; }
                else if (st2 == 1) { MBAR_WAIT(mb + 8,  ph1); ph1 ^= 1; }
                else               { MBAR_WAIT(mb + 16, ph2); ph2 ^= 1; }
            }
            load_tile128h(Ab, K, c + 2, stg + st2 * STAGE_B, tid);
            load_tile128h(Bb, K, c + 2, stg + st2 * STAGE_B + TILE_B, tid);
            CP_COMMIT();
        }
    }
    {
        const int stl = (nch - 1) % 3;
        if (stl == 0)      MBAR_WAIT(mb,      ph0);
        else if (stl == 1) MBAR_WAIT(mb + 8,  ph1);
        else               MBAR_WAIT(mb + 16, ph2);
    }
    asm volatile("tcgen05.fence::after_thread_sync;" ::: "memory");
    return tmem;
}

#endif  // __CUDA_ARCH_FEAT_SM103_ALL

// ---------------------------------------------------------------------------
// Legacy GEMM core (fallback; round-13 proven schedule)
// ---------------------------------------------------------------------------
__device__ __forceinline__ void gemm_main_h(const __half* __restrict__ A, int lda,
                                            const __half* __restrict__ B, int ldb,
                                            int K, char* smem, int tid,
                                            float (&d)[4][8][4]) {
    const int warp   = tid >> 5;
    const int lane   = tid & 31;
    const int warp_m = (warp >> 1) * 64;
    const int warp_n = (warp & 1) * 64;
    const int row    = lane >> 2;
    const int col    = lane & 3;

    #pragma unroll
    for (int mt = 0; mt < 4; mt++)
        #pragma unroll
        for (int nt = 0; nt < 8; nt++)
            #pragma unroll
            for (int j = 0; j < 4; j++) d[mt][nt][j] = 0.0f;

    const int nch = K / 64;
    load_tile128h(A, lda, 0, smem, tid);
    load_tile128h(B, ldb, 0, smem + TILE_B, tid);
    CP_COMMIT();
    load_tile128h(A, lda, 1, smem + STAGE_B, tid);
    load_tile128h(B, ldb, 1, smem + STAGE_B + TILE_B, tid);
    CP_COMMIT();

    for (int c = 0; c < nch; c++) {
        if (c + 1 < nch) CP_WAIT(1);
        else             CP_WAIT(0);
        __syncthreads();

        if (c + 2 < nch) {
            char* st = smem + ((c + 2) % 3) * STAGE_B;
            load_tile128h(A, lda, c + 2, st, tid);
            load_tile128h(B, ldb, c + 2, st + TILE_B, tid);
            CP_COMMIT();
        }

        const char* Asb = smem + (c % 3) * STAGE_B;
        const char* Bsb = Asb + TILE_B;

        #pragma unroll
        for (int ks = 0; ks < 4; ks++) {
            const int ck   = ks * 2;
            const int swz0 = ((ck ^ (row & 7)) * 16) + 4 * col;
            const int swz1 = (((ck + 1) ^ (row & 7)) * 16) + 4 * col;

            uint32_t a[4][4];
            #pragma unroll
            for (int mt = 0; mt < 4; mt++) {
                const char* ap0 = Asb + (warp_m + mt * 16 + row) * 128;
                const char* ap8 = ap0 + 8 * 128;
                a[mt][0] = *(const uint32_t*)(ap0 + swz0);
                a[mt][1] = *(const uint32_t*)(ap8 + swz0);
                a[mt][2] = *(const uint32_t*)(ap0 + swz1);
                a[mt][3] = *(const uint32_t*)(ap8 + swz1);
            }
            uint32_t b[8][2];
            #pragma unroll
            for (int nt = 0; nt < 8; nt++) {
                const char* bp = Bsb + (warp_n + nt * 8 + row) * 128;
                b[nt][0] = *(const uint32_t*)(bp + swz0);
                b[nt][1] = *(const uint32_t*)(bp + swz1);
            }
            #pragma unroll
            for (int mt = 0; mt < 4; mt++)
                #pragma unroll
                for (int nt = 0; nt < 8; nt++)
                    mma_f16(d[mt][nt], a[mt], b[nt]);
        }
    }
}

// ---------------------------------------------------------------------------
// Generic GEMM kernels (fp16 in, weights pre-transposed)
//   EPI 2: half(gelu(acc + bias)) -> half C   EPI 3: fp32 C += acc + bias
// ---------------------------------------------------------------------------
template <int EPI>
__global__ __launch_bounds__(128, 2)
void tgemm_kernel(const __half* __restrict__ A, const __half* __restrict__ Bt,
                  const float* __restrict__ bias, void* __restrict__ Cv,
                  int Ncols, int K) {
    extern __shared__ __align__(1024) char smem[];
    const int tid  = threadIdx.x;
    const int warp = tid >> 5;
    const int lane = tid & 31;
    const int m0 = blockIdx.y * 128;
    const int n0 = blockIdx.x * 128;

#if defined(HAS_TCGEN05)
    const uint32_t tmem = tc_gemm_main(A + (size_t)m0 * K, Bt + (size_t)n0 * K,
                                       K, smem, tid);

    const int rrow = m0 + warp * 32 + lane;
    #pragma unroll
    for (int nb = 0; nb < 4; nb++) {
        uint32_t r[32];
        TC_LD_X32(r, tmem + nb * 32);
        asm volatile("tcgen05.wait::ld.sync.aligned;" ::: "memory");
        const int ncol = n0 + nb * 32;
        if (EPI == 2) {
            __half* crow = (__half*)Cv + (size_t)rrow * Ncols + ncol;
            #pragma unroll
            for (int j = 0; j < 32; j += 2) {
                float v0 = __uint_as_float(r[j])     + bias[ncol + j];
                float v1 = __uint_as_float(r[j + 1]) + bias[ncol + j + 1];
                v0 = 0.5f * v0 * (1.0f + erff(v0 * 0.70710678118654752f));
                v1 = 0.5f * v1 * (1.0f + erff(v1 * 0.70710678118654752f));
                *(__half2*)(crow + j) = __floats2half2_rn(v0, v1);
            }
        } else {
            float* crow = (float*)Cv + (size_t)rrow * Ncols + ncol;
            #pragma unroll
            for (int j = 0; j < 32; j += 4) {
                float4 old = *(float4*)(crow + j);
                old.x += __uint_as_float(r[j])     + bias[ncol + j];
                old.y += __uint_as_float(r[j + 1]) + bias[ncol + j + 1];
                old.z += __uint_as_float(r[j + 2]) + bias[ncol + j + 2];
                old.w += __uint_as_float(r[j + 3]) + bias[ncol + j + 3];
                *(float4*)(crow + j) = old;
            }
        }
    }
    asm volatile("tcgen05.fence::before_thread_sync;" ::: "memory");
    __syncthreads();
    if (warp == 0) TC_DEALLOC(tmem, 128);

#else
    float d[4][8][4];
    gemm_main_h(A + (size_t)m0 * K, K, Bt + (size_t)n0 * K, K, K, smem, tid, d);

    const int warp_m = (warp >> 1) * 64;
    const int warp_n = (warp & 1) * 64;
    const int row = lane >> 2, col = lane & 3;

    #pragma unroll
    for (int nt = 0; nt < 8; nt++) {
        const int nb = n0 + warp_n + nt * 8 + col * 2;
        const float2 bv = *(const float2*)(bias + nb);
        #pragma unroll
        for (int mt = 0; mt < 4; mt++) {
            const int m1 = m0 + warp_m + mt * 16 + row;
            #pragma unroll
            for (int half_i = 0; half_i < 2; half_i++) {
                const int mr = m1 + half_i * 8;
                float v0 = d[mt][nt][half_i * 2 + 0] + bv.x;
                float v1 = d[mt][nt][half_i * 2 + 1] + bv.y;
                if (EPI == 2) {
                    v0 = 0.5f * v0 * (1.0f + erff(v0 * 0.70710678118654752f));
                    v1 = 0.5f * v1 * (1.0f + erff(v1 * 0.70710678118654752f));
                    __half* crow = (__half*)Cv + (size_t)mr * Ncols + nb;
                    *(__half2*)crow = __floats2half2_rn(v0, v1);
                } else {
                    float* crow = (float*)Cv + (size_t)mr * Ncols + nb;
                    const float2 old = *(const float2*)crow;
                    *(float2*)crow = make_float2(v0 + old.x, v1 + old.y);
                }
            }
        }
    }
#endif
}

// ---------------------------------------------------------------------------
// Fused QKV projection: grid.x = 12 -> (sel = x>>2) in {q,k,v}, n0 = (x&3)*128
// Q: scaled fp16.  K: fp16.  V: smem-staged transposed write to vt.
// tcgen05 path on the sm_103a feature pass; legacy fallback otherwise.
// ---------------------------------------------------------------------------
#define VT_STRIDE 144   // halves per staged row (288 B, 16B-aligned)

__global__ __launch_bounds__(128, 2)
void qkv_kernel(const __half* __restrict__ A,
                const __half* __restrict__ wqt, const __half* __restrict__ wkt,
                const __half* __restrict__ wvt,
                const float* __restrict__ bq, const float* __restrict__ bk,
                const float* __restrict__ bv,
                __half* __restrict__ q, __half* __restrict__ k,
                __half* __restrict__ vt) {
    extern __shared__ __align__(1024) char smem[];
    const int tid  = threadIdx.x;
    const int warp = tid >> 5;
    const int lane = tid & 31;
    const int sel = blockIdx.x >> 2;
    const int n0  = (blockIdx.x & 3) * 128;
    const int m0  = blockIdx.y * 128;

    const __half* Bt  = (sel == 0) ? wqt : (sel == 1) ? wkt : wvt;
    const float* bias = (sel == 0) ? bq  : (sel == 1) ? bk  : bv;
    const float scale = (sel == 0) ? 0.125f : 1.0f;

#if defined(HAS_TCGEN05)
    const uint32_t tmem = tc_gemm_main(A + (size_t)m0 * HDIM,
                                       Bt + (size_t)n0 * HDIM, HDIM, smem, tid);

    const int rrow = m0 + warp * 32 + lane;     // global m-row
    if (sel < 2) {
        __half* C = (sel == 0) ? q : k;
        #pragma unroll
        for (int nb = 0; nb < 4; nb++) {
            uint32_t r[32];
            TC_LD_X32(r, tmem + nb * 32);
            asm volatile("tcgen05.wait::ld.sync.aligned;" ::: "memory");
            const int ncol = n0 + nb * 32;
            __half* crow = C + (size_t)rrow * HDIM + ncol;
            #pragma unroll
            for (int j = 0; j < 32; j += 2) {
                const float v0 = (__uint_as_float(r[j])     + bias[ncol + j])     * scale;
                const float v1 = (__uint_as_float(r[j + 1]) + bias[ncol + j + 1]) * scale;
                *(__half2*)(crow + j) = __floats2half2_rn(v0, v1);
            }
        }
        asm volatile("tcgen05.fence::before_thread_sync;" ::: "memory");
        __syncthreads();
        if (warp == 0) TC_DEALLOC(tmem, 128);
    } else {
        // V: stage [n_local][m_local] in (dead) pipeline smem, then
        // coalesced transposed write-out to vt[bh][d][j].
        __half* tp = (__half*)(smem + 1024);    // [128][VT_STRIDE]
        const int ml = warp * 32 + lane;        // local m 0..127
        #pragma unroll
        for (int nb = 0; nb < 4; nb++) {
            uint32_t r[32];
            TC_LD_X32(r, tmem + nb * 32);
            asm volatile("tcgen05.wait::ld.sync.aligned;" ::: "memory");
            const int ncol = n0 + nb * 32;
            #pragma unroll
            for (int j = 0; j < 32; j++) {
                tp[(nb * 32 + j) * VT_STRIDE + ml] =
                    __float2half_rn(__uint_as_float(r[j]) + bias[ncol + j]);
            }
        }
        asm volatile("tcgen05.fence::before_thread_sync;" ::: "memory");
        __syncthreads();
        if (warp == 0) TC_DEALLOC(tmem, 128);

        const int bb = m0 >> 8;
        const int j0 = m0 & 255;
        const int chunk = tid & 15;
        const int rsub  = tid >> 4;
        #pragma unroll
        for (int it = 0; it < 16; it++) {
            const int nl = it * 8 + rsub;
            const int h  = (n0 + nl) >> 6;
            const int dd = (n0 + nl) & 63;
            const uint4 val = *(const uint4*)(tp + nl * VT_STRIDE + chunk * 8);
            __half* dst = vt + ((size_t)(bb * 8 + h) * DHEAD + dd) * NSEQ + j0;
            *(uint4*)(dst + chunk * 8) = val;
        }
    }

#else
    float d[4][8][4];
    gemm_main_h(A + (size_t)m0 * HDIM, HDIM, Bt + (size_t)n0 * HDIM, HDIM, HDIM,
                smem, tid, d);

    const int warp_m = (warp >> 1) * 64;
    const int warp_n = (warp & 1) * 64;
    const int row = lane >> 2, col = lane & 3;

    if (sel < 2) {
        __half* C = (sel == 0) ? q : k;
        #pragma unroll
        for (int nt = 0; nt < 8; nt++) {
            const int nb = n0 + warp_n + nt * 8 + col * 2;
            const float2 bvv = *(const float2*)(bias + nb);
            #pragma unroll
            for (int mt = 0; mt < 4; mt++) {
                const int m1 = m0 + warp_m + mt * 16 + row;
                #pragma unroll
                for (int half_i = 0; half_i < 2; half_i++) {
                    __half* crow = C + (size_t)(m1 + half_i * 8) * HDIM + nb;
                    const float v0 = (d[mt][nt][half_i * 2 + 0] + bvv.x) * scale;
                    const float v1 = (d[mt][nt][half_i * 2 + 1] + bvv.y) * scale;
                    *(__half2*)crow = __floats2half2_rn(v0, v1);
                }
            }
        }
    } else {
        __syncthreads();
        __half* tp = (__half*)smem;   // [128][VT_STRIDE]
        #pragma unroll
        for (int nt = 0; nt < 8; nt++) {
            const int nl = warp_n + nt * 8 + col * 2;
            const float2 bvv = *(const float2*)(bias + n0 + nl);
            #pragma unroll
            for (int mt = 0; mt < 4; mt++) {
                #pragma unroll
                for (int half_i = 0; half_i < 2; half_i++) {
                    const int ml = warp_m + mt * 16 + row + half_i * 8;
                    tp[nl * VT_STRIDE + ml] =
                        __float2half_rn(d[mt][nt][half_i * 2 + 0] + bvv.x);
                    tp[(nl + 1) * VT_STRIDE + ml] =
                        __float2half_rn(d[mt][nt][half_i * 2 + 1] + bvv.y);
                }
            }
        }
        __syncthreads();

        const int bb = m0 >> 8;
        const int j0 = m0 & 255;
        const int chunk = tid & 15;
        const int rsub  = tid >> 4;
        #pragma unroll
        for (int it = 0; it < 16; it++) {
            const int nl = it * 8 + rsub;
            const int h  = (n0 + nl) >> 6;
            const int dd = (n0 + nl) & 63;
            const uint4 val = *(const uint4*)(tp + nl * VT_STRIDE + chunk * 8);
            __half* dst = vt + ((size_t)(bb * 8 + h) * DHEAD + dd) * NSEQ + j0;
            *(uint4*)(dst + chunk * 8) = val;
        }
    }
#endif
}

// ---------------------------------------------------------------------------
// Fused flash attention (fp16 operands): ctx = softmax(Q·K^T + bias) · V
// ---------------------------------------------------------------------------
#define FA_STAGE 16384
#define FA_SMEM  (16384 + 2 * FA_STAGE)   // 49152

__device__ __forceinline__ void load_kv_h(const __half* __restrict__ Kb,
                                          const __half* __restrict__ Vb,
                                          int j0, char* st, int tid) {
    char* Ks = st;
    char* Vs = st + 8192;
    #pragma unroll
    for (int i = 0; i < 2; i++) {
        const int id = tid + i * 256;
        const int r  = id >> 3;
        const int ck = id & 7;
        const int off = r * 128 + ((ck ^ (r & 7)) * 16);
        cp_async16(Ks + off, Kb + (size_t)(j0 + r) * HDIM + ck * 8);
        cp_async16(Vs + off, Vb + (size_t)r * NSEQ + j0 + ck * 8);
    }
}

__global__ __launch_bounds__(256, 2)
void fattn_kernel(const __half* __restrict__ q, const __half* __restrict__ k,
                  const __half* __restrict__ vt, const float* __restrict__ attn_bias,
                  __half* __restrict__ ctx) {
    extern __shared__ __align__(16) char smem[];
    char* QP    = smem;
    char* stage = smem + 16384;

    const int tid  = threadIdx.x;
    const int warp = tid >> 5;
    const int lane = tid & 31;
    const int row  = lane >> 2;
    const int col  = lane & 3;
    const int bh = blockIdx.y;
    const int b  = bh >> 3, h = bh & 7;
    const int m0 = blockIdx.x * 128;

    const __half* Qb = q  + (size_t)b * NSEQ * HDIM + (size_t)m0 * HDIM + h * DHEAD;
    const __half* Kb = k  + (size_t)b * NSEQ * HDIM + h * DHEAD;
    const __half* Vb = vt + (size_t)bh * DHEAD * NSEQ;

    #pragma unroll
    for (int i = 0; i < 4; i++) {
        const int id = tid + i * 256;
        const int r  = id >> 3;
        const int ck = id & 7;
        const int off = r * 128 + ((ck ^ (r & 7)) * 16);
        cp_async16(QP + off, Qb + (size_t)r * HDIM + ck * 8);
    }
    CP_COMMIT();
    load_kv_h(Kb, Vb, 0, stage, tid);
    CP_COMMIT();

    CP_WAIT(1);
    __syncthreads();
    uint32_t aq[4][4];
    #pragma unroll
    for (int ks = 0; ks < 4; ks++) {
        const int ck   = ks * 2;
        const int swz0 = ((ck ^ (row & 7)) * 16) + 4 * col;
        const int swz1 = (((ck + 1) ^ (row & 7)) * 16) + 4 * col;
        const char* ap0 = QP + (warp * 16 + row) * 128;
        const char* ap8 = ap0 + 8 * 128;
        aq[ks][0] = *(const uint32_t*)(ap0 + swz0);
        aq[ks][1] = *(const uint32_t*)(ap8 + swz0);
        aq[ks][2] = *(const uint32_t*)(ap0 + swz1);
        aq[ks][3] = *(const uint32_t*)(ap8 + swz1);
    }
    __syncthreads();

    float m0r = -1e30f, m1r = -1e30f, l0 = 0.0f, l1 = 0.0f;
    float cacc[8][4];
    #pragma unroll
    for (int nt = 0; nt < 8; nt++)
        #pragma unroll
        for (int j = 0; j < 4; j++) cacc[nt][j] = 0.0f;

    const float* bias_b = attn_bias + (size_t)bh * NSEQ * NSEQ
                        + (size_t)(m0 + warp * 16 + row) * NSEQ;
    char* Pw = QP + warp * 2048;

    for (int c = 0; c < 4; c++) {
        CP_WAIT(0);
        __syncthreads();
        if (c < 3) {
            load_kv_h(Kb, Vb, (c + 1) * 64, stage + ((c + 1) & 1) * FA_STAGE, tid);
            CP_COMMIT();
        }

        const char* Ksb = stage + (c & 1) * FA_STAGE;
        const char* Vsb = Ksb + 8192;

        float s[8][4];
        #pragma unroll
        for (int nt = 0; nt < 8; nt++)
            #pragma unroll
            for (int j = 0; j < 4; j++) s[nt][j] = 0.0f;

        #pragma unroll
        for (int ks = 0; ks < 4; ks++) {
            const int ck   = ks * 2;
            const int swz0 = ((ck ^ (row & 7)) * 16) + 4 * col;
            const int swz1 = (((ck + 1) ^ (row & 7)) * 16) + 4 * col;
            uint32_t bfr[8][2];
            #pragma unroll
            for (int nt = 0; nt < 8; nt++) {
                const char* bp = Ksb + (nt * 8 + row) * 128;
                bfr[nt][0] = *(const uint32_t*)(bp + swz0);
                bfr[nt][1] = *(const uint32_t*)(bp + swz1);
            }
            #pragma unroll
            for (int nt = 0; nt < 8; nt++)
                mma_f16(s[nt], aq[ks], bfr[nt]);
        }

        float mx0 = -1e30f, mx1 = -1e30f;
        #pragma unroll
        for (int nt = 0; nt < 8; nt++) {
            const float* bp = bias_b + c * 64 + nt * 8 + 2 * col;
            const float2 b0 = *(const float2*)bp;
            const float2 b1 = *(const float2*)(bp + 8 * NSEQ);
            s[nt][0] += b0.x; s[nt][1] += b0.y;
            s[nt][2] += b1.x; s[nt][3] += b1.y;
            mx0 = fmaxf(mx0, fmaxf(s[nt][0], s[nt][1]));
            mx1 = fmaxf(mx1, fmaxf(s[nt][2], s[nt][3]));
        }
        mx0 = fmaxf(mx0, __shfl_xor_sync(0xffffffffu, mx0, 1));
        mx0 = fmaxf(mx0, __shfl_xor_sync(0xffffffffu, mx0, 2));
        mx1 = fmaxf(mx1, __shfl_xor_sync(0xffffffffu, mx1, 1));
        mx1 = fmaxf(mx1, __shfl_xor_sync(0xffffffffu, mx1, 2));

        const float mn0 = fmaxf(m0r, mx0);
        const float mn1 = fmaxf(m1r, mx1);
        const float f0 = __expf(m0r - mn0);
        const float f1 = __expf(m1r - mn1);
        m0r = mn0; m1r = mn1;

        float sum0 = 0.0f, sum1 = 0.0f;
        #pragma unroll
        for (int nt = 0; nt < 8; nt++) {
            s[nt][0] = __expf(s[nt][0] - mn0);
            s[nt][1] = __expf(s[nt][1] - mn0);
            s[nt][2] = __expf(s[nt][2] - mn1);
            s[nt][3] = __expf(s[nt][3] - mn1);
            sum0 += s[nt][0] + s[nt][1];
            sum1 += s[nt][2] + s[nt][3];
        }
        l0 = l0 * f0 + sum0;
        l1 = l1 * f1 + sum1;
        #pragma unroll
        for (int nt = 0; nt < 8; nt++) {
            cacc[nt][0] *= f0; cacc[nt][1] *= f0;
            cacc[nt][2] *= f1; cacc[nt][3] *= f1;
        }

        #pragma unroll
        for (int nt = 0; nt < 8; nt++) {
            const int swzp = ((nt ^ (row & 7)) * 16) + 4 * col;
            *(__half2*)(Pw + row * 128 + swzp) =
                __floats2half2_rn(s[nt][0], s[nt][1]);
            *(__half2*)(Pw + (row + 8) * 128 + swzp) =
                __floats2half2_rn(s[nt][2], s[nt][3]);
        }
        __syncwarp();

        #pragma unroll
        for (int ks = 0; ks < 4; ks++) {
            const int ck   = ks * 2;
            const int swz0 = ((ck ^ (row & 7)) * 16) + 4 * col;
            const int swz1 = (((ck + 1) ^ (row & 7)) * 16) + 4 * col;
            const char* pp0 = Pw + row * 128;
            const char* pp8 = pp0 + 8 * 128;
            uint32_t a[4];
            a[0] = *(const uint32_t*)(pp0 + swz0);
            a[1] = *(const uint32_t*)(pp8 + swz0);
            a[2] = *(const uint32_t*)(pp0 + swz1);
            a[3] = *(const uint32_t*)(pp8 + swz1);
            uint32_t bfr[8][2];
            #pragma unroll
            for (int nt = 0; nt < 8; nt++) {
                const char* bp = Vsb + (nt * 8 + row) * 128;
                bfr[nt][0] = *(const uint32_t*)(bp + swz0);
                bfr[nt][1] = *(const uint32_t*)(bp + swz1);
            }
            #pragma unroll
            for (int nt = 0; nt < 8; nt++)
                mma_f16(cacc[nt], a, bfr[nt]);
        }
        __syncwarp();
    }

    l0 += __shfl_xor_sync(0xffffffffu, l0, 1);
    l0 += __shfl_xor_sync(0xffffffffu, l0, 2);
    l1 += __shfl_xor_sync(0xffffffffu, l1, 1);
    l1 += __shfl_xor_sync(0xffffffffu, l1, 2);
    const float inv0 = 1.0f / l0;
    const float inv1 = 1.0f / l1;

    __half* Cb = ctx + (size_t)b * NSEQ * HDIM + h * DHEAD
               + (size_t)(m0 + warp * 16 + row) * HDIM;
    #pragma unroll
    for (int nt = 0; nt < 8; nt++) {
        const int nb = nt * 8 + 2 * col;
        *(__half2*)(Cb + nb) =
            __floats2half2_rn(cacc[nt][0] * inv0, cacc[nt][1] * inv0);
        *(__half2*)(Cb + 8 * HDIM + nb) =
            __floats2half2_rn(cacc[nt][2] * inv1, cacc[nt][3] * inv1);
    }
}

// ---------------------------------------------------------------------------
// Weight transpose + fp16 convert: dst[n][k] = half(src[k][n]) per layer
// ---------------------------------------------------------------------------
__global__ void transpose_kernel(const float* __restrict__ src,
                                 __half* __restrict__ dst, int R, int C) {
    __shared__ float t[32][33];
    const size_t lo = (size_t)blockIdx.z * R * C;
    const int c0 = blockIdx.x * 32, r0 = blockIdx.y * 32;
    #pragma unroll
    for (int i = 0; i < 32; i += 8)
        t[threadIdx.y + i][threadIdx.x] =
            src[lo + (size_t)(r0 + threadIdx.y + i) * C + c0 + threadIdx.x];
    __syncthreads();
    #pragma unroll
    for (int i = 0; i < 32; i += 8)
        dst[lo + (size_t)(c0 + threadIdx.y + i) * R + r0 + threadIdx.x] =
            __float2half_rn(t[threadIdx.x][threadIdx.y + i]);
}

// ---------------------------------------------------------------------------
// LayerNorm: warp-per-row, float4 loads, shfl reductions, fp16 out
// ---------------------------------------------------------------------------
__global__ __launch_bounds__(256)
void ln_kernel(const float* __restrict__ x,
               const float* __restrict__ gs,
               const float* __restrict__ gb,
               __half* __restrict__ y) {
    const int warp = threadIdx.x >> 5;
    const int lane = threadIdx.x & 31;
    const int row  = blockIdx.x * 8 + warp;

    const float4* xr = (const float4*)(x + (size_t)row * HDIM);
    float4 v[4];
    float s = 0.0f;
    #pragma unroll
    for (int j = 0; j < 4; j++) {
        v[j] = xr[j * 32 + lane];
        s += v[j].x + v[j].y + v[j].z + v[j].w;
    }
    #pragma unroll
    for (int o = 16; o; o >>= 1) s += __shfl_xor_sync(0xffffffffu, s, o);
    const float mu = s * (1.0f / HDIM);

    float sq = 0.0f;
    #pragma unroll
    for (int j = 0; j < 4; j++) {
        v[j].x -= mu; v[j].y -= mu; v[j].z -= mu; v[j].w -= mu;
        sq += v[j].x * v[j].x + v[j].y * v[j].y + v[j].z * v[j].z + v[j].w * v[j].w;
    }
    #pragma unroll
    for (int o = 16; o; o >>= 1) sq += __shfl_xor_sync(0xffffffffu, sq, o);
    const float inv = rsqrtf(sq * (1.0f / HDIM) + 1e-5f);

    const float4* gs4 = (const float4*)gs;
    const float4* gb4 = (const float4*)gb;
    uint2* yr = (uint2*)(y + (size_t)row * HDIM);
    #pragma unroll
    for (int j = 0; j < 4; j++) {
        const int idx = j * 32 + lane;
        const float4 g = gs4[idx];
        const float4 bb = gb4[idx];
        const __half2 lo = __floats2half2_rn(v[j].x * inv * g.x + bb.x,
                                             v[j].y * inv * g.y + bb.y);
        const __half2 hi = __floats2half2_rn(v[j].z * inv * g.z + bb.z,
                                             v[j].w * inv * g.w + bb.w);
        uint2 pk;
        pk.x = *(const uint32_t*)&lo;
        pk.y = *(const uint32_t*)&hi;
        yr[idx] = pk;
    }
}

// ---------------------------------------------------------------------------
// Host launcher
// ---------------------------------------------------------------------------
extern "C" void kernel_launch(void* const* d_in, const int* in_sizes, int n_in,
                              void* d_out, int out_size) {
    const float* x_in      = (const float*)d_in[0];
    const float* attn_bias = (const float*)d_in[1];
    const float* ln1_s     = (const float*)d_in[2];
    const float* ln1_b     = (const float*)d_in[3];
    const float* wq        = (const float*)d_in[4];
    const float* bq        = (const float*)d_in[5];
    const float* wk        = (const float*)d_in[6];
    const float* bk        = (const float*)d_in[7];
    const float* wv        = (const float*)d_in[8];
    const float* bv        = (const float*)d_in[9];
    const float* wo        = (const float*)d_in[10];
    const float* bo        = (const float*)d_in[11];
    const float* ln2_s     = (const float*)d_in[12];
    const float* ln2_b     = (const float*)d_in[13];
    const float* w1        = (const float*)d_in[14];
    const float* b1        = (const float*)d_in[15];
    const float* w2        = (const float*)d_in[16];
    const float* b2        = (const float*)d_in[17];

    float* X = (float*)d_out;

    __half *yb, *qb, *kb, *cb, *fb, *vt;
    __half *wqt, *wkt, *wvt, *wot, *w1t, *w2t;
    cudaGetSymbolAddress((void**)&yb, g_y);
    cudaGetSymbolAddress((void**)&qb, g_q);
    cudaGetSymbolAddress((void**)&kb, g_k);
    cudaGetSymbolAddress((void**)&cb, g_ctx);
    cudaGetSymbolAddress((void**)&fb, g_ffn);
    cudaGetSymbolAddress((void**)&vt, g_vt);
    cudaGetSymbolAddress((void**)&wqt, g_wqt);
    cudaGetSymbolAddress((void**)&wkt, g_wkt);
    cudaGetSymbolAddress((void**)&wvt, g_wvt);
    cudaGetSymbolAddress((void**)&wot, g_wot);
    cudaGetSymbolAddress((void**)&w1t, g_w1t);
    cudaGetSymbolAddress((void**)&w2t, g_w2t);

    cudaFuncSetAttribute(tgemm_kernel<2>,
                         cudaFuncAttributeMaxDynamicSharedMemorySize, GSMEM_TC);
    cudaFuncSetAttribute(tgemm_kernel<3>,
                         cudaFuncAttributeMaxDynamicSharedMemorySize, GSMEM_TC);
    cudaFuncSetAttribute(qkv_kernel,
                         cudaFuncAttributeMaxDynamicSharedMemorySize, GSMEM_TC);
    cudaFuncSetAttribute(fattn_kernel,
                         cudaFuncAttributeMaxDynamicSharedMemorySize, FA_SMEM);

    cudaMemcpyAsync(X, x_in, (size_t)MROWS * HDIM * sizeof(float),
                    cudaMemcpyDeviceToDevice);

    // One-time weight transposes (+ fp16 convert)
    {
        const dim3 tb(32, 8);
        const dim3 gHH(HDIM / 32, HDIM / 32, LNUM);
        const dim3 gHF(FDIM / 32, HDIM / 32, LNUM);
        const dim3 gFH(HDIM / 32, FDIM / 32, LNUM);
        transpose_kernel<<<gHH, tb>>>(wq, wqt, HDIM, HDIM);
        transpose_kernel<<<gHH, tb>>>(wk, wkt, HDIM, HDIM);
        transpose_kernel<<<gHH, tb>>>(wv, wvt, HDIM, HDIM);
        transpose_kernel<<<gHH, tb>>>(wo, wot, HDIM, HDIM);
        transpose_kernel<<<gHF, tb>>>(w1, w1t, HDIM, FDIM);
        transpose_kernel<<<gFH, tb>>>(w2, w2t, FDIM, HDIM);
    }

    const dim3 gB(256);
    const dim3 tG(128);
    const dim3 gLN(MROWS / 8);                   // 1024 blocks, warp-per-row
    const dim3 gQKV(12, MROWS / 128);            // (12, 64)
    const dim3 gProj(HDIM / 128, MROWS / 128);   // (4, 64)
    const dim3 gFfn1(FDIM / 128, MROWS / 128);   // (16, 64)
    const dim3 gFA(NSEQ / 128, NBH);             // (2, 256)

    for (int l = 0; l < LNUM; l++) {
        const __half* wqt_l = wqt + (size_t)l * HDIM * HDIM;
        const __half* wkt_l = wkt + (size_t)l * HDIM * HDIM;
        const __half* wvt_l = wvt + (size_t)l * HDIM * HDIM;
        const __half* wot_l = wot + (size_t)l * HDIM * HDIM;
        const __half* w1t_l = w1t + (size_t)l * HDIM * FDIM;
        const __half* w2t_l = w2t + (size_t)l * FDIM * HDIM;

        // --- attention block ---
        ln_kernel<<<gLN, gB>>>(X, ln1_s + l * HDIM, ln1_b + l * HDIM, yb);
        qkv_kernel<<<gQKV, tG, GSMEM_TC>>>(yb, wqt_l, wkt_l, wvt_l,
                                           bq + l * HDIM, bk + l * HDIM, bv + l * HDIM,
                                           qb, kb, vt);
        fattn_kernel<<<gFA, gB, FA_SMEM>>>(qb, kb, vt, attn_bias, cb);
        tgemm_kernel<3><<<gProj, tG, GSMEM_TC>>>(cb, wot_l, bo + l * HDIM, X,
                                                 HDIM, HDIM);

        // --- FFN block ---
        ln_kernel<<<gLN, gB>>>(X, ln2_s + l * HDIM, ln2_b + l * HDIM, yb);
        tgemm_kernel<2><<<gFfn1, tG, GSMEM_TC>>>(yb, w1t_l, b1 + l * FDIM, fb,
                                                 FDIM, HDIM);
        tgemm_kernel<3><<<gProj, tG, GSMEM_TC>>>(fb, w2t_l, b2 + l * HDIM, X,
                                                 HDIM, FDIM);
    }
}